// round 12
// baseline (speedup 1.0000x reference)
#include <cuda_runtime.h>
#include <cstdint>

// ---------------------------------------------------------------------------
// Problem constants
// ---------------------------------------------------------------------------
#define BB   4
#define SS   2048
#define DIM  1024
#define HH   16
#define HD   64
#define MB   16
#define NMB  128           // S / MB
#define NB   11            // CP + DEG
#define NKNOTS 15
#define EPSV 1e-6f
#define TPITCH 768         // 12 * 64 floats per m-block in tokbuf

// ---------------------------------------------------------------------------
// Device scratch (no cudaMalloc allowed)
// ---------------------------------------------------------------------------
__device__ float g_Q[(size_t)BB * HH * SS * HD];   // (b,h,s,d)
__device__ float g_K[(size_t)BB * HH * SS * HD];
__device__ float g_V[(size_t)BB * HH * SS * HD];
__device__ float g_Y[(size_t)BB * SS * DIM];       // (b,s,dim) -> LN in place
__device__ float g_eta[(size_t)BB * HH * NMB * MB];
__device__ float g_cos[SS * (HD / 2)];
__device__ float g_sin[SS * (HD / 2)];

// ---------------------------------------------------------------------------
// Helpers
// ---------------------------------------------------------------------------
__device__ __forceinline__ void wsum2(float &a, float &b) {
#pragma unroll
    for (int o = 16; o > 0; o >>= 1) {
        a += __shfl_xor_sync(0xffffffffu, a, o);
        b += __shfl_xor_sync(0xffffffffu, b, o);
    }
}

__device__ __forceinline__ uint32_t f2tf32(float x) {
    uint32_t r;
    asm("cvt.rna.tf32.f32 %0, %1;" : "=r"(r) : "f"(x));
    return r;
}

__device__ __forceinline__ uint4 cvt4(uint4 v) {
    uint4 r;
    r.x = f2tf32(__uint_as_float(v.x));
    r.y = f2tf32(__uint_as_float(v.y));
    r.z = f2tf32(__uint_as_float(v.z));
    r.w = f2tf32(__uint_as_float(v.w));
    return r;
}

__device__ __forceinline__ void mma_tf32(float *d, const uint32_t *a,
                                         const uint32_t *b) {
    asm volatile(
        "mma.sync.aligned.m16n8k8.row.col.f32.tf32.tf32.f32 "
        "{%0,%1,%2,%3}, {%4,%5,%6,%7}, {%8,%9}, {%0,%1,%2,%3};\n"
        : "+f"(d[0]), "+f"(d[1]), "+f"(d[2]), "+f"(d[3])
        : "r"(a[0]), "r"(a[1]), "r"(a[2]), "r"(a[3]), "r"(b[0]), "r"(b[1]));
}

// Sparse uniform-knot cubic B-spline: at most 4 nonzero basis values.
__device__ __forceinline__ void bspline4(float x, float kn0, float inv_h,
                                         int &jbase, float (&w)[4]) {
    float u = (x - kn0) * inv_h;
    float fi = floorf(u);
    float t = u - fi;
    int idx = (int)fi;
    bool valid = (u >= 0.0f) && (u < 14.0f);
    float t2 = t * t, t3 = t2 * t;
    float omt = 1.0f - t;
    const float s = 1.0f / 6.0f;
    jbase = idx - 3;
    float w0 = omt * omt * omt * s;
    float w1 = fmaf(3.f, t3, fmaf(-6.f, t2, 4.f)) * s;
    float w2 = fmaf(-3.f, t3, fmaf(3.f, t2, fmaf(3.f, t, 1.f))) * s;
    float w3 = t3 * s;
    w[0] = (valid && jbase >= 0 && jbase <= 10) ? w0 : 0.f;
    w[1] = (valid && jbase + 1 >= 0 && jbase + 1 <= 10) ? w1 : 0.f;
    w[2] = (valid && jbase + 2 >= 0 && jbase + 2 <= 10) ? w2 : 0.f;
    w[3] = (valid && jbase + 3 <= 10) ? w3 : 0.f;
}

__device__ __forceinline__ int clampj(int j) {
    return j < 0 ? 0 : (j > 10 ? 10 : j);
}

// ---------------------------------------------------------------------------
// RoPE table: double-precision cos/sin of the fp32 angles
// ---------------------------------------------------------------------------
__global__ void rope_tab_kernel(const float *__restrict__ posf) {
    int i = blockIdx.x * blockDim.x + threadIdx.x;
    if (i < SS * (HD / 2)) {
        double a = (double)posf[i];
        g_cos[i] = (float)cos(a);
        g_sin[i] = (float)sin(a);
    }
}

// ---------------------------------------------------------------------------
// 1xTF32 tensor-core GEMM core: R7 layout, MINIMAL double-buffer (1 bar/tile)
// C(128x128) = A(128xK) * W(128xK)^T ; 256 thr = 8 warps 2(M)x4(N)
// ---------------------------------------------------------------------------
#define SPITCH 20            // smem row pitch (uint32)
#define SBUFU (128 * SPITCH) // one buffer, in uint32

__device__ __forceinline__ void stage_tile(uint32_t *As, uint32_t *Bs,
                                           int r0, int c4,
                                           uint4 va0, uint4 va1,
                                           uint4 vb0, uint4 vb1) {
    *(uint4 *)&As[r0 * SPITCH + c4] = cvt4(va0);
    *(uint4 *)&As[(r0 + 64) * SPITCH + c4] = cvt4(va1);
    *(uint4 *)&Bs[r0 * SPITCH + c4] = cvt4(vb0);
    *(uint4 *)&Bs[(r0 + 64) * SPITCH + c4] = cvt4(vb1);
}

__device__ __forceinline__ void tc_gemm_core(
    const float *__restrict__ A, const float *__restrict__ B,
    uint32_t *As, uint32_t *Bs,   // each [2][SBUFU]
    float (&acc)[4][4][4], int rowBase, int colBase) {
    int tid = threadIdx.x;
    int lane = tid & 31, wid = tid >> 5;
    int wm = wid >> 2, wn = wid & 3;
    int r0 = tid >> 2, c4 = (tid & 3) << 2;

    const uint4 *pA = (const uint4 *)(A + (size_t)(rowBase + r0) * 1024 + c4);
    const uint4 *pB = (const uint4 *)(B + (size_t)(colBase + r0) * 1024 + c4);
    const int rstep = 64 * 1024 / 4;   // +64 rows, in uint4 units

    // stage k-tile 0 into buffer 0
    uint4 va0 = pA[0], va1 = pA[rstep];
    uint4 vb0 = pB[0], vb1 = pB[rstep];
    stage_tile(As, Bs, r0, c4, va0, va1, vb0, vb1);
    // prefetch k-tile 1
    va0 = pA[4]; va1 = pA[4 + rstep];
    vb0 = pB[4]; vb1 = pB[4 + rstep];

    int cur = 0;
    for (int k0 = 0; k0 < 1024; k0 += 16) {
        __syncthreads();   // buf[cur] stores visible; buf[cur^1] reads drained
        if (k0 + 16 < 1024) {
            uint32_t off = (uint32_t)(cur ^ 1) * SBUFU;
            stage_tile(As + off, Bs + off, r0, c4, va0, va1, vb0, vb1);
            if (k0 + 32 < 1024) {
                int ko = (k0 + 32) >> 2;
                va0 = pA[ko]; va1 = pA[ko + rstep];
                vb0 = pB[ko]; vb1 = pB[ko + rstep];
            }
        }
        const uint32_t *Ac = As + (uint32_t)cur * SBUFU;
        const uint32_t *Bc = Bs + (uint32_t)cur * SBUFU;
#pragma unroll
        for (int ks = 0; ks < 2; ks++) {
            int kb = ks * 8 + (lane & 3);
            uint32_t ah[4][4], bh[4][2];
#pragma unroll
            for (int mt = 0; mt < 4; mt++) {
                int row = wm * 64 + mt * 16 + (lane >> 2);
                ah[mt][0] = Ac[row * SPITCH + kb];
                ah[mt][1] = Ac[(row + 8) * SPITCH + kb];
                ah[mt][2] = Ac[row * SPITCH + kb + 4];
                ah[mt][3] = Ac[(row + 8) * SPITCH + kb + 4];
            }
#pragma unroll
            for (int nt = 0; nt < 4; nt++) {
                int col = wn * 32 + nt * 8 + (lane >> 2);
                bh[nt][0] = Bc[col * SPITCH + kb];
                bh[nt][1] = Bc[col * SPITCH + kb + 4];
            }
#pragma unroll
            for (int mt = 0; mt < 4; mt++)
#pragma unroll
                for (int nt = 0; nt < 4; nt++)
                    mma_tf32(acc[mt][nt], ah[mt], bh[nt]);
        }
        cur ^= 1;
    }
}

// QKV projection + RoPE, scattering into (b,h,s,d) layout. blockIdx.z in {0,1,2}
__global__ __launch_bounds__(256) void tc_qkv_kernel(
    const float *__restrict__ x, const float *__restrict__ Wq,
    const float *__restrict__ Wk, const float *__restrict__ Wv) {
    __shared__ uint32_t As[2 * SBUFU], Bs[2 * SBUFU];
    const float *W = (blockIdx.z == 0) ? Wq : (blockIdx.z == 1) ? Wk : Wv;
    float *O = (blockIdx.z == 0) ? g_Q : (blockIdx.z == 1) ? g_K : g_V;

    float acc[4][4][4];
#pragma unroll
    for (int a = 0; a < 4; a++)
#pragma unroll
        for (int b = 0; b < 4; b++)
#pragma unroll
            for (int c = 0; c < 4; c++) acc[a][b][c] = 0.f;

    int rowBase = blockIdx.y * 128, colBase = blockIdx.x * 128;
    tc_gemm_core(x, W, As, Bs, acc, rowBase, colBase);

    int lane = threadIdx.x & 31, wid = threadIdx.x >> 5;
    int wm = wid >> 2, wn = wid & 3;
#pragma unroll
    for (int mt = 0; mt < 4; mt++) {
        int r = rowBase + wm * 64 + mt * 16 + (lane >> 2);
#pragma unroll
        for (int half = 0; half < 2; half++) {
            int ri = r + half * 8;
            int b = ri >> 11;  // S = 2048
            int s = ri & 2047;
#pragma unroll
            for (int nt = 0; nt < 4; nt++) {
                int c = colBase + wn * 32 + nt * 8 + 2 * (lane & 3);
                int h = c >> 6;
                int dd = c & 63;
                int jj = dd >> 1;
                float cs = g_cos[s * 32 + jj];
                float sn = g_sin[s * 32 + jj];
                float t1 = acc[mt][nt][2 * half];
                float t2 = acc[mt][nt][2 * half + 1];
                size_t o = (((size_t)(b * HH + h) * SS) + s) * HD + dd;
                O[o]     = t1 * cs - t2 * sn;
                O[o + 1] = t1 * sn + t2 * cs;
            }
        }
    }
}

// Final projection: d_out = Y_normalized @ Wo^T
__global__ __launch_bounds__(256) void tc_out_kernel(const float *__restrict__ Wo,
                                                     float *__restrict__ out) {
    __shared__ uint32_t As[2 * SBUFU], Bs[2 * SBUFU];
    float acc[4][4][4];
#pragma unroll
    for (int a = 0; a < 4; a++)
#pragma unroll
        for (int b = 0; b < 4; b++)
#pragma unroll
            for (int c = 0; c < 4; c++) acc[a][b][c] = 0.f;

    int rowBase = blockIdx.y * 128, colBase = blockIdx.x * 128;
    tc_gemm_core(g_Y, Wo, As, Bs, acc, rowBase, colBase);

    int lane = threadIdx.x & 31, wid = threadIdx.x >> 5;
    int wm = wid >> 2, wn = wid & 3;
#pragma unroll
    for (int mt = 0; mt < 4; mt++) {
        int r = rowBase + wm * 64 + mt * 16 + (lane >> 2);
#pragma unroll
        for (int half = 0; half < 2; half++) {
            size_t ri = r + half * 8;
#pragma unroll
            for (int nt = 0; nt < 4; nt++) {
                int c = colBase + wn * 32 + nt * 8 + 2 * (lane & 3);
                float2 v = make_float2(acc[mt][nt][2 * half],
                                       acc[mt][nt][2 * half + 1]);
                *(float2 *)(out + ri * 1024 + c) = v;
            }
        }
    }
}

// ---------------------------------------------------------------------------
// eta = sigmoid(x . lr_W[h] + lr_b[h]) / HD * gs[m]
// ---------------------------------------------------------------------------
__global__ __launch_bounds__(128) void eta_kernel(
    const float *__restrict__ x, const float *__restrict__ lrW,
    const float *__restrict__ lrb, const float *__restrict__ gsc) {
    int row = blockIdx.x;  // b*2048 + s
    __shared__ float xs[1024];
    const float4 *xp = (const float4 *)(x + (size_t)row * 1024);
    float4 *xsp = (float4 *)xs;
    xsp[threadIdx.x] = xp[threadIdx.x];
    xsp[threadIdx.x + 128] = xp[threadIdx.x + 128];
    __syncthreads();

    int w = threadIdx.x >> 5, l = threadIdx.x & 31;
    int b = row >> 11, s = row & 2047;
    int n = s >> 4, m = s & 15;
    float gs = fmaxf(1.0f / (float)(m + 1) + gsc[m], 0.0f);

#pragma unroll
    for (int hh = 0; hh < 4; hh++) {
        int h = w * 4 + hh;
        const float *wp = lrW + (size_t)h * 1024;
        float sum = 0.f;
        for (int k = l; k < 1024; k += 32) sum = fmaf(xs[k], wp[k], sum);
#pragma unroll
        for (int o = 16; o > 0; o >>= 1) sum += __shfl_xor_sync(0xffffffffu, sum, o);
        if (l == 0) {
            float lr = 1.0f / (1.0f + __expf(-(sum + lrb[h]))) * (1.0f / 64.0f);
            g_eta[(((size_t)b * HH + h) * NMB + n) * MB + m] = lr * gs;
        }
    }
}

// ---------------------------------------------------------------------------
// Sequential TTT scan (R11 version: register-batched cumsum)
// ---------------------------------------------------------------------------
__global__ __launch_bounds__(512) void scan_kernel(
    const float *__restrict__ gamma, const float *__restrict__ beta,
    const float *__restrict__ knots, const float *__restrict__ coeff) {
    extern __shared__ float sm[];
    float *tokbuf = sm;                       // [MB][12][HD]
    float *Wsbuf = sm + MB * TPITCH;          // [2][NB*HD]

    int bh = blockIdx.x;
    int b = bh >> 4, h = bh & 15;
    int tid = threadIdx.x, m = tid >> 5, l = tid & 31;

    float kn0 = knots[0];
    float kn14 = knots[NKNOTS - 1];
    float inv_h = 14.0f / (kn14 - kn0);

    float g0 = gamma[h * HD + l], g1 = gamma[h * HD + l + 32];
    float be0 = beta[h * HD + l], be1 = beta[h * HD + l + 32];

    for (int idx = tid; idx < NB * HD; idx += 512)
        Wsbuf[idx] = coeff[(size_t)h * NB * HD + idx];

    const float *Qb = g_Q + (size_t)bh * SS * HD;
    const float *Kb = g_K + (size_t)bh * SS * HD;
    const float *Vb = g_V + (size_t)bh * SS * HD;
    const float *eb = g_eta + (size_t)bh * NMB * MB;
    float *Yb = g_Y + (size_t)b * SS * DIM + h * HD;

    float *cbase = tokbuf + (tid >> 4) * HD + ((tid & 15) << 2);
    float *mb = tokbuf + m * TPITCH;

    int cur = 0;
    __syncthreads();

    int base0 = m * HD + l;
    float q0 = Qb[base0], q1 = Qb[base0 + 32];
    float k0 = Kb[base0], k1 = Kb[base0 + 32];
    float v0 = Vb[base0], v1 = Vb[base0 + 32];
    float e  = eb[m];

    for (int n = 0; n < NMB; n++) {
        float cq0 = q0, cq1 = q1, ck0 = k0, ck1 = k1, cv0 = v0, cv1 = v1, ce = e;
        int np = (n + 1 < NMB) ? n + 1 : n;
        int basen = (np * MB + m) * HD + l;
        q0 = Qb[basen]; q1 = Qb[basen + 32];
        k0 = Kb[basen]; k1 = Kb[basen + 32];
        v0 = Vb[basen]; v1 = Vb[basen + 32];
        e  = eb[np * MB + m];

        const float *Wc = Wsbuf + cur * (NB * HD);
        float *Wn = Wsbuf + (cur ^ 1) * (NB * HD);

        int jk0, jk1;
        float wk0[4], wk1[4];
        bspline4(ck0, kn0, inv_h, jk0, wk0);
        bspline4(ck1, kn0, inv_h, jk1, wk1);

        float z0 = __fdividef(ck0, 1.0f + __expf(-ck0));
        float z1 = __fdividef(ck1, 1.0f + __expf(-ck1));
#pragma unroll
        for (int k = 0; k < 4; k++) {
            z0 = fmaf(wk0[k], Wc[clampj(jk0 + k) * HD + l], z0);
            z1 = fmaf(wk1[k], Wc[clampj(jk1 + k) * HD + l + 32], z1);
        }
        float s1 = z0 + z1, s2 = fmaf(z0, z0, z1 * z1);
        wsum2(s1, s2);
        float mu = s1 * (1.f / 64.f);
        float var = s2 * (1.f / 64.f) - mu * mu;
        float rstd = rsqrtf(var + EPSV);
        float xh0 = (z0 - mu) * rstd, xh1 = (z1 - mu) * rstd;
        float gh0 = (fmaf(g0, xh0, be0) - (cv0 - ck0)) * g0;
        float gh1 = (fmaf(g1, xh1, be1) - (cv1 - ck1)) * g1;
        s1 = gh0 + gh1;
        s2 = fmaf(gh0, xh0, gh1 * xh1);
        wsum2(s1, s2);
        float mg = s1 * (1.f / 64.f), mgx = s2 * (1.f / 64.f);
        float eg0 = ce * (gh0 - mg - xh0 * mgx) * rstd;
        float eg1 = ce * (gh1 - mg - xh1 * mgx) * rstd;

        float4 z4 = make_float4(0.f, 0.f, 0.f, 0.f);
#pragma unroll
        for (int i = 0; i < 6; i++)
            ((float4 *)mb)[i * 32 + l] = z4;
        __syncwarp();
#pragma unroll
        for (int k = 0; k < 4; k++) {
            if (wk0[k] != 0.f) mb[(jk0 + k) * HD + l] = eg0 * wk0[k];
            if (wk1[k] != 0.f) mb[(jk1 + k) * HD + l + 32] = eg1 * wk1[k];
        }
        __syncthreads();

        // ---- phase B: cumsum over m, register-batched (2 x 8) ----
        if (tid < 176) {
            float4 vv[8];
            float4 carry = make_float4(0.f, 0.f, 0.f, 0.f);
#pragma unroll
            for (int blk = 0; blk < 2; blk++) {
                float *p = cbase + blk * 8 * TPITCH;
#pragma unroll
                for (int mm = 0; mm < 8; mm++)
                    vv[mm] = *(float4 *)(p + mm * TPITCH);
                vv[0].x += carry.x; vv[0].y += carry.y;
                vv[0].z += carry.z; vv[0].w += carry.w;
#pragma unroll
                for (int mm = 1; mm < 8; mm++) {
                    vv[mm].x += vv[mm - 1].x; vv[mm].y += vv[mm - 1].y;
                    vv[mm].z += vv[mm - 1].z; vv[mm].w += vv[mm - 1].w;
                }
#pragma unroll
                for (int mm = 0; mm < 8; mm++)
                    *(float4 *)(p + mm * TPITCH) = vv[mm];
                carry = vv[7];
            }
        }
        __syncthreads();

        int jq0, jq1;
        float wq0[4], wq1[4];
        bspline4(cq0, kn0, inv_h, jq0, wq0);
        bspline4(cq1, kn0, inv_h, jq1, wq1);
        float zq0 = __fdividef(cq0, 1.0f + __expf(-cq0));
        float zq1 = __fdividef(cq1, 1.0f + __expf(-cq1));
#pragma unroll
        for (int k = 0; k < 4; k++) {
            int ja = clampj(jq0 + k) * HD + l;
            int jb = clampj(jq1 + k) * HD + l + 32;
            zq0 = fmaf(wq0[k], Wc[ja] - mb[ja], zq0);
            zq1 = fmaf(wq1[k], Wc[jb] - mb[jb], zq1);
        }
        s1 = zq0 + zq1;
        s2 = fmaf(zq0, zq0, zq1 * zq1);
        wsum2(s1, s2);
        mu = s1 * (1.f / 64.f);
        var = s2 * (1.f / 64.f) - mu * mu;
        rstd = rsqrtf(var + EPSV);
        float y0 = cq0 + fmaf(g0, (zq0 - mu) * rstd, be0);
        float y1 = cq1 + fmaf(g1, (zq1 - mu) * rstd, be1);

        size_t yo = (size_t)(n * MB + m) * DIM;
        Yb[yo + l] = y0;
        Yb[yo + l + 32] = y1;

        if (tid < 176) {
            const float4 wv = *(const float4 *)(Wc + tid * 4);
            const float4 cv = *(const float4 *)(tokbuf + 15 * TPITCH + tid * 4);
            float4 r;
            r.x = wv.x - cv.x; r.y = wv.y - cv.y;
            r.z = wv.z - cv.z; r.w = wv.w - cv.w;
            *(float4 *)(Wn + tid * 4) = r;
        }
        __syncthreads();
        cur ^= 1;
    }
}

// ---------------------------------------------------------------------------
// Final layernorm over DIM, in place on g_Y
// ---------------------------------------------------------------------------
__global__ __launch_bounds__(256) void ln_kernel(const float *__restrict__ pw,
                                                 const float *__restrict__ pb) {
    int row = blockIdx.x;
    int tid = threadIdx.x;
    float4 v = *((const float4 *)(g_Y + (size_t)row * 1024) + tid);
    float s1 = v.x + v.y + v.z + v.w;
    float s2 = v.x * v.x + v.y * v.y + v.z * v.z + v.w * v.w;
    wsum2(s1, s2);
    __shared__ float sa[8], sb[8];
    int w = tid >> 5, l = tid & 31;
    if (l == 0) { sa[w] = s1; sb[w] = s2; }
    __syncthreads();
    s1 = 0.f; s2 = 0.f;
#pragma unroll
    for (int i = 0; i < 8; i++) { s1 += sa[i]; s2 += sb[i]; }
    float mu = s1 * (1.f / 1024.f);
    float var = s2 * (1.f / 1024.f) - mu * mu;
    float rstd = rsqrtf(var + EPSV);
    float4 pwv = *((const float4 *)pw + tid);
    float4 pbv = *((const float4 *)pb + tid);
    float4 o;
    o.x = (v.x - mu) * rstd * pwv.x + pbv.x;
    o.y = (v.y - mu) * rstd * pwv.y + pbv.y;
    o.z = (v.z - mu) * rstd * pwv.z + pbv.z;
    o.w = (v.w - mu) * rstd * pwv.w + pbv.w;
    *((float4 *)(g_Y + (size_t)row * 1024) + tid) = o;
}

// ---------------------------------------------------------------------------
// Launch
// ---------------------------------------------------------------------------
extern "C" void kernel_launch(void *const *d_in, const int *in_sizes, int n_in,
                              void *d_out, int out_size) {
    const float *x     = (const float *)d_in[0];
    const float *posf  = (const float *)d_in[1];
    const float *Wq    = (const float *)d_in[2];
    const float *Wk    = (const float *)d_in[3];
    const float *Wv    = (const float *)d_in[4];
    const float *Wo    = (const float *)d_in[5];
    const float *lrW   = (const float *)d_in[6];
    const float *lrb   = (const float *)d_in[7];
    const float *gsc   = (const float *)d_in[8];
    const float *tgam  = (const float *)d_in[9];
    const float *tbet  = (const float *)d_in[10];
    const float *postw = (const float *)d_in[11];
    const float *postb = (const float *)d_in[12];
    const float *coeff = (const float *)d_in[13];
    const float *knots = (const float *)d_in[14];
    float *out = (float *)d_out;

    const int scan_smem = (MB * TPITCH + 2 * NB * HD) * sizeof(float);  // 54784 B
    cudaFuncSetAttribute(scan_kernel, cudaFuncAttributeMaxDynamicSharedMemorySize,
                         scan_smem);

    rope_tab_kernel<<<(SS * (HD / 2) + 1023) / 1024, 1024>>>(posf);
    tc_qkv_kernel<<<dim3(DIM / 128, BB * SS / 128, 3), 256>>>(x, Wq, Wk, Wv);
    eta_kernel<<<BB * SS, 128>>>(x, lrW, lrb, gsc);
    scan_kernel<<<BB * HH, 512, scan_smem>>>(tgam, tbet, knots, coeff);
    ln_kernel<<<BB * SS, 256>>>(postw, postb);
    tc_out_kernel<<<dim3(DIM / 128, BB * SS / 128, 1), 256>>>(Wo, out);
}

// round 13
// speedup vs baseline: 1.0537x; 1.0537x over previous
#include <cuda_runtime.h>
#include <cstdint>

// ---------------------------------------------------------------------------
// Problem constants
// ---------------------------------------------------------------------------
#define BB   4
#define SS   2048
#define DIM  1024
#define HH   16
#define HD   64
#define MB   16
#define NMB  128           // S / MB
#define NB   11            // CP + DEG
#define NKNOTS 15
#define EPSV 1e-6f
#define TPITCH 768         // 12 * 64 floats per m-block in tokbuf

// ---------------------------------------------------------------------------
// Device scratch (no cudaMalloc allowed)
// ---------------------------------------------------------------------------
__device__ float g_Q[(size_t)BB * HH * SS * HD];   // (b,h,s,d)
__device__ float g_K[(size_t)BB * HH * SS * HD];
__device__ float g_V[(size_t)BB * HH * SS * HD];
__device__ float g_Y[(size_t)BB * SS * DIM];       // (b,s,dim) -> LN in place
__device__ float g_eta[(size_t)BB * HH * NMB * MB];
__device__ float g_cos[SS * (HD / 2)];
__device__ float g_sin[SS * (HD / 2)];

// ---------------------------------------------------------------------------
// Helpers
// ---------------------------------------------------------------------------
__device__ __forceinline__ void wsum2(float &a, float &b) {
#pragma unroll
    for (int o = 16; o > 0; o >>= 1) {
        a += __shfl_xor_sync(0xffffffffu, a, o);
        b += __shfl_xor_sync(0xffffffffu, b, o);
    }
}

__device__ __forceinline__ uint32_t f2tf32(float x) {
    uint32_t r;
    asm("cvt.rna.tf32.f32 %0, %1;" : "=r"(r) : "f"(x));
    return r;
}

__device__ __forceinline__ uint4 cvt4(uint4 v) {
    uint4 r;
    r.x = f2tf32(__uint_as_float(v.x));
    r.y = f2tf32(__uint_as_float(v.y));
    r.z = f2tf32(__uint_as_float(v.z));
    r.w = f2tf32(__uint_as_float(v.w));
    return r;
}

__device__ __forceinline__ void mma_tf32(float *d, const uint32_t *a,
                                         const uint32_t *b) {
    asm volatile(
        "mma.sync.aligned.m16n8k8.row.col.f32.tf32.tf32.f32 "
        "{%0,%1,%2,%3}, {%4,%5,%6,%7}, {%8,%9}, {%0,%1,%2,%3};\n"
        : "+f"(d[0]), "+f"(d[1]), "+f"(d[2]), "+f"(d[3])
        : "r"(a[0]), "r"(a[1]), "r"(a[2]), "r"(a[3]), "r"(b[0]), "r"(b[1]));
}

// Sparse uniform-knot cubic B-spline: at most 4 nonzero basis values.
__device__ __forceinline__ void bspline4(float x, float kn0, float inv_h,
                                         int &jbase, float (&w)[4]) {
    float u = (x - kn0) * inv_h;
    float fi = floorf(u);
    float t = u - fi;
    int idx = (int)fi;
    bool valid = (u >= 0.0f) && (u < 14.0f);
    float t2 = t * t, t3 = t2 * t;
    float omt = 1.0f - t;
    const float s = 1.0f / 6.0f;
    jbase = idx - 3;
    float w0 = omt * omt * omt * s;
    float w1 = fmaf(3.f, t3, fmaf(-6.f, t2, 4.f)) * s;
    float w2 = fmaf(-3.f, t3, fmaf(3.f, t2, fmaf(3.f, t, 1.f))) * s;
    float w3 = t3 * s;
    w[0] = (valid && jbase >= 0 && jbase <= 10) ? w0 : 0.f;
    w[1] = (valid && jbase + 1 >= 0 && jbase + 1 <= 10) ? w1 : 0.f;
    w[2] = (valid && jbase + 2 >= 0 && jbase + 2 <= 10) ? w2 : 0.f;
    w[3] = (valid && jbase + 3 <= 10) ? w3 : 0.f;
}

__device__ __forceinline__ int clampj(int j) {
    return j < 0 ? 0 : (j > 10 ? 10 : j);
}

// ---------------------------------------------------------------------------
// RoPE table: double-precision cos/sin of the fp32 angles
// ---------------------------------------------------------------------------
__global__ void rope_tab_kernel(const float *__restrict__ posf) {
    int i = blockIdx.x * blockDim.x + threadIdx.x;
    if (i < SS * (HD / 2)) {
        double a = (double)posf[i];
        g_cos[i] = (float)cos(a);
        g_sin[i] = (float)sin(a);
    }
}

// ---------------------------------------------------------------------------
// 1xTF32 tensor-core GEMM core (exact R7 winner: single buffer, 2 bars/tile)
// C(128x128) = A(128xK) * W(128xK)^T ; 256 thr = 8 warps 2(M)x4(N)
// ---------------------------------------------------------------------------
#define SPITCH 20   // smem row pitch (uint32) — 16B-aligned stores, conflict-free

__device__ __forceinline__ void tc_gemm_core(
    const float *__restrict__ A, const float *__restrict__ B,
    uint32_t *As, uint32_t *Bs,
    float (&acc)[4][4][4], int rowBase, int colBase) {
    int tid = threadIdx.x;
    int lane = tid & 31, wid = tid >> 5;
    int wm = wid >> 2, wn = wid & 3;
    int r0 = tid >> 2, c4 = (tid & 3) << 2;

    const uint4 *pA = (const uint4 *)(A + (size_t)(rowBase + r0) * 1024 + c4);
    const uint4 *pB = (const uint4 *)(B + (size_t)(colBase + r0) * 1024 + c4);
    const int rstep = 64 * 1024 / 4;   // +64 rows, in uint4 units

    uint4 va0 = pA[0], va1 = pA[rstep];
    uint4 vb0 = pB[0], vb1 = pB[rstep];

    for (int k0 = 0; k0 < 1024; k0 += 16) {
        __syncthreads();
        *(uint4 *)&As[r0 * SPITCH + c4] = cvt4(va0);
        *(uint4 *)&As[(r0 + 64) * SPITCH + c4] = cvt4(va1);
        *(uint4 *)&Bs[r0 * SPITCH + c4] = cvt4(vb0);
        *(uint4 *)&Bs[(r0 + 64) * SPITCH + c4] = cvt4(vb1);
        __syncthreads();
        if (k0 + 16 < 1024) {
            int ko = (k0 + 16) >> 2;
            va0 = pA[ko]; va1 = pA[ko + rstep];
            vb0 = pB[ko]; vb1 = pB[ko + rstep];
        }
#pragma unroll
        for (int ks = 0; ks < 2; ks++) {
            int kb = ks * 8 + (lane & 3);
            uint32_t ah[4][4], bh[4][2];
#pragma unroll
            for (int mt = 0; mt < 4; mt++) {
                int row = wm * 64 + mt * 16 + (lane >> 2);
                ah[mt][0] = As[row * SPITCH + kb];
                ah[mt][1] = As[(row + 8) * SPITCH + kb];
                ah[mt][2] = As[row * SPITCH + kb + 4];
                ah[mt][3] = As[(row + 8) * SPITCH + kb + 4];
            }
#pragma unroll
            for (int nt = 0; nt < 4; nt++) {
                int col = wn * 32 + nt * 8 + (lane >> 2);
                bh[nt][0] = Bs[col * SPITCH + kb];
                bh[nt][1] = Bs[col * SPITCH + kb + 4];
            }
#pragma unroll
            for (int mt = 0; mt < 4; mt++)
#pragma unroll
                for (int nt = 0; nt < 4; nt++)
                    mma_tf32(acc[mt][nt], ah[mt], bh[nt]);
        }
    }
}

// QKV projection + RoPE, scattering into (b,h,s,d) layout. blockIdx.z in {0,1,2}
__global__ __launch_bounds__(256) void tc_qkv_kernel(
    const float *__restrict__ x, const float *__restrict__ Wq,
    const float *__restrict__ Wk, const float *__restrict__ Wv) {
    __shared__ uint32_t As[128 * SPITCH], Bs[128 * SPITCH];
    const float *W = (blockIdx.z == 0) ? Wq : (blockIdx.z == 1) ? Wk : Wv;
    float *O = (blockIdx.z == 0) ? g_Q : (blockIdx.z == 1) ? g_K : g_V;

    float acc[4][4][4];
#pragma unroll
    for (int a = 0; a < 4; a++)
#pragma unroll
        for (int b = 0; b < 4; b++)
#pragma unroll
            for (int c = 0; c < 4; c++) acc[a][b][c] = 0.f;

    int rowBase = blockIdx.y * 128, colBase = blockIdx.x * 128;
    tc_gemm_core(x, W, As, Bs, acc, rowBase, colBase);

    int lane = threadIdx.x & 31, wid = threadIdx.x >> 5;
    int wm = wid >> 2, wn = wid & 3;
#pragma unroll
    for (int mt = 0; mt < 4; mt++) {
        int r = rowBase + wm * 64 + mt * 16 + (lane >> 2);
#pragma unroll
        for (int half = 0; half < 2; half++) {
            int ri = r + half * 8;
            int b = ri >> 11;  // S = 2048
            int s = ri & 2047;
#pragma unroll
            for (int nt = 0; nt < 4; nt++) {
                int c = colBase + wn * 32 + nt * 8 + 2 * (lane & 3);
                int h = c >> 6;
                int dd = c & 63;
                int jj = dd >> 1;
                float cs = g_cos[s * 32 + jj];
                float sn = g_sin[s * 32 + jj];
                float t1 = acc[mt][nt][2 * half];
                float t2 = acc[mt][nt][2 * half + 1];
                size_t o = (((size_t)(b * HH + h) * SS) + s) * HD + dd;
                O[o]     = t1 * cs - t2 * sn;
                O[o + 1] = t1 * sn + t2 * cs;
            }
        }
    }
}

// Final projection: d_out = Y_normalized @ Wo^T
__global__ __launch_bounds__(256) void tc_out_kernel(const float *__restrict__ Wo,
                                                     float *__restrict__ out) {
    __shared__ uint32_t As[128 * SPITCH], Bs[128 * SPITCH];
    float acc[4][4][4];
#pragma unroll
    for (int a = 0; a < 4; a++)
#pragma unroll
        for (int b = 0; b < 4; b++)
#pragma unroll
            for (int c = 0; c < 4; c++) acc[a][b][c] = 0.f;

    int rowBase = blockIdx.y * 128, colBase = blockIdx.x * 128;
    tc_gemm_core(g_Y, Wo, As, Bs, acc, rowBase, colBase);

    int lane = threadIdx.x & 31, wid = threadIdx.x >> 5;
    int wm = wid >> 2, wn = wid & 3;
#pragma unroll
    for (int mt = 0; mt < 4; mt++) {
        int r = rowBase + wm * 64 + mt * 16 + (lane >> 2);
#pragma unroll
        for (int half = 0; half < 2; half++) {
            size_t ri = r + half * 8;
#pragma unroll
            for (int nt = 0; nt < 4; nt++) {
                int c = colBase + wn * 32 + nt * 8 + 2 * (lane & 3);
                float2 v = make_float2(acc[mt][nt][2 * half],
                                       acc[mt][nt][2 * half + 1]);
                *(float2 *)(out + ri * 1024 + c) = v;
            }
        }
    }
}

// ---------------------------------------------------------------------------
// eta = sigmoid(x . lr_W[h] + lr_b[h]) / HD * gs[m]
// ---------------------------------------------------------------------------
__global__ __launch_bounds__(128) void eta_kernel(
    const float *__restrict__ x, const float *__restrict__ lrW,
    const float *__restrict__ lrb, const float *__restrict__ gsc) {
    int row = blockIdx.x;  // b*2048 + s
    __shared__ float xs[1024];
    const float4 *xp = (const float4 *)(x + (size_t)row * 1024);
    float4 *xsp = (float4 *)xs;
    xsp[threadIdx.x] = xp[threadIdx.x];
    xsp[threadIdx.x + 128] = xp[threadIdx.x + 128];
    __syncthreads();

    int w = threadIdx.x >> 5, l = threadIdx.x & 31;
    int b = row >> 11, s = row & 2047;
    int n = s >> 4, m = s & 15;
    float gs = fmaxf(1.0f / (float)(m + 1) + gsc[m], 0.0f);

#pragma unroll
    for (int hh = 0; hh < 4; hh++) {
        int h = w * 4 + hh;
        const float *wp = lrW + (size_t)h * 1024;
        float sum = 0.f;
        for (int k = l; k < 1024; k += 32) sum = fmaf(xs[k], wp[k], sum);
#pragma unroll
        for (int o = 16; o > 0; o >>= 1) sum += __shfl_xor_sync(0xffffffffu, sum, o);
        if (l == 0) {
            float lr = 1.0f / (1.0f + __expf(-(sum + lrb[h]))) * (1.0f / 64.0f);
            g_eta[(((size_t)b * HH + h) * NMB + n) * MB + m] = lr * gs;
        }
    }
}

// ---------------------------------------------------------------------------
// Sequential TTT scan (R11 version: register-batched cumsum)
// ---------------------------------------------------------------------------
__global__ __launch_bounds__(512) void scan_kernel(
    const float *__restrict__ gamma, const float *__restrict__ beta,
    const float *__restrict__ knots, const float *__restrict__ coeff) {
    extern __shared__ float sm[];
    float *tokbuf = sm;                       // [MB][12][HD]
    float *Wsbuf = sm + MB * TPITCH;          // [2][NB*HD]

    int bh = blockIdx.x;
    int b = bh >> 4, h = bh & 15;
    int tid = threadIdx.x, m = tid >> 5, l = tid & 31;

    float kn0 = knots[0];
    float kn14 = knots[NKNOTS - 1];
    float inv_h = 14.0f / (kn14 - kn0);

    float g0 = gamma[h * HD + l], g1 = gamma[h * HD + l + 32];
    float be0 = beta[h * HD + l], be1 = beta[h * HD + l + 32];

    for (int idx = tid; idx < NB * HD; idx += 512)
        Wsbuf[idx] = coeff[(size_t)h * NB * HD + idx];

    const float *Qb = g_Q + (size_t)bh * SS * HD;
    const float *Kb = g_K + (size_t)bh * SS * HD;
    const float *Vb = g_V + (size_t)bh * SS * HD;
    const float *eb = g_eta + (size_t)bh * NMB * MB;
    float *Yb = g_Y + (size_t)b * SS * DIM + h * HD;

    float *cbase = tokbuf + (tid >> 4) * HD + ((tid & 15) << 2);
    float *mb = tokbuf + m * TPITCH;

    int cur = 0;
    __syncthreads();

    int base0 = m * HD + l;
    float q0 = Qb[base0], q1 = Qb[base0 + 32];
    float k0 = Kb[base0], k1 = Kb[base0 + 32];
    float v0 = Vb[base0], v1 = Vb[base0 + 32];
    float e  = eb[m];

    for (int n = 0; n < NMB; n++) {
        float cq0 = q0, cq1 = q1, ck0 = k0, ck1 = k1, cv0 = v0, cv1 = v1, ce = e;
        int np = (n + 1 < NMB) ? n + 1 : n;
        int basen = (np * MB + m) * HD + l;
        q0 = Qb[basen]; q1 = Qb[basen + 32];
        k0 = Kb[basen]; k1 = Kb[basen + 32];
        v0 = Vb[basen]; v1 = Vb[basen + 32];
        e  = eb[np * MB + m];

        const float *Wc = Wsbuf + cur * (NB * HD);
        float *Wn = Wsbuf + (cur ^ 1) * (NB * HD);

        int jk0, jk1;
        float wk0[4], wk1[4];
        bspline4(ck0, kn0, inv_h, jk0, wk0);
        bspline4(ck1, kn0, inv_h, jk1, wk1);

        float z0 = __fdividef(ck0, 1.0f + __expf(-ck0));
        float z1 = __fdividef(ck1, 1.0f + __expf(-ck1));
#pragma unroll
        for (int k = 0; k < 4; k++) {
            z0 = fmaf(wk0[k], Wc[clampj(jk0 + k) * HD + l], z0);
            z1 = fmaf(wk1[k], Wc[clampj(jk1 + k) * HD + l + 32], z1);
        }
        float s1 = z0 + z1, s2 = fmaf(z0, z0, z1 * z1);
        wsum2(s1, s2);
        float mu = s1 * (1.f / 64.f);
        float var = s2 * (1.f / 64.f) - mu * mu;
        float rstd = rsqrtf(var + EPSV);
        float xh0 = (z0 - mu) * rstd, xh1 = (z1 - mu) * rstd;
        float gh0 = (fmaf(g0, xh0, be0) - (cv0 - ck0)) * g0;
        float gh1 = (fmaf(g1, xh1, be1) - (cv1 - ck1)) * g1;
        s1 = gh0 + gh1;
        s2 = fmaf(gh0, xh0, gh1 * xh1);
        wsum2(s1, s2);
        float mg = s1 * (1.f / 64.f), mgx = s2 * (1.f / 64.f);
        float eg0 = ce * (gh0 - mg - xh0 * mgx) * rstd;
        float eg1 = ce * (gh1 - mg - xh1 * mgx) * rstd;

        float4 z4 = make_float4(0.f, 0.f, 0.f, 0.f);
#pragma unroll
        for (int i = 0; i < 6; i++)
            ((float4 *)mb)[i * 32 + l] = z4;
        __syncwarp();
#pragma unroll
        for (int k = 0; k < 4; k++) {
            if (wk0[k] != 0.f) mb[(jk0 + k) * HD + l] = eg0 * wk0[k];
            if (wk1[k] != 0.f) mb[(jk1 + k) * HD + l + 32] = eg1 * wk1[k];
        }
        __syncthreads();

        // ---- phase B: cumsum over m, register-batched (2 x 8) ----
        if (tid < 176) {
            float4 vv[8];
            float4 carry = make_float4(0.f, 0.f, 0.f, 0.f);
#pragma unroll
            for (int blk = 0; blk < 2; blk++) {
                float *p = cbase + blk * 8 * TPITCH;
#pragma unroll
                for (int mm = 0; mm < 8; mm++)
                    vv[mm] = *(float4 *)(p + mm * TPITCH);
                vv[0].x += carry.x; vv[0].y += carry.y;
                vv[0].z += carry.z; vv[0].w += carry.w;
#pragma unroll
                for (int mm = 1; mm < 8; mm++) {
                    vv[mm].x += vv[mm - 1].x; vv[mm].y += vv[mm - 1].y;
                    vv[mm].z += vv[mm - 1].z; vv[mm].w += vv[mm - 1].w;
                }
#pragma unroll
                for (int mm = 0; mm < 8; mm++)
                    *(float4 *)(p + mm * TPITCH) = vv[mm];
                carry = vv[7];
            }
        }
        __syncthreads();

        int jq0, jq1;
        float wq0[4], wq1[4];
        bspline4(cq0, kn0, inv_h, jq0, wq0);
        bspline4(cq1, kn0, inv_h, jq1, wq1);
        float zq0 = __fdividef(cq0, 1.0f + __expf(-cq0));
        float zq1 = __fdividef(cq1, 1.0f + __expf(-cq1));
#pragma unroll
        for (int k = 0; k < 4; k++) {
            int ja = clampj(jq0 + k) * HD + l;
            int jb = clampj(jq1 + k) * HD + l + 32;
            zq0 = fmaf(wq0[k], Wc[ja] - mb[ja], zq0);
            zq1 = fmaf(wq1[k], Wc[jb] - mb[jb], zq1);
        }
        s1 = zq0 + zq1;
        s2 = fmaf(zq0, zq0, zq1 * zq1);
        wsum2(s1, s2);
        mu = s1 * (1.f / 64.f);
        var = s2 * (1.f / 64.f) - mu * mu;
        rstd = rsqrtf(var + EPSV);
        float y0 = cq0 + fmaf(g0, (zq0 - mu) * rstd, be0);
        float y1 = cq1 + fmaf(g1, (zq1 - mu) * rstd, be1);

        size_t yo = (size_t)(n * MB + m) * DIM;
        Yb[yo + l] = y0;
        Yb[yo + l + 32] = y1;

        if (tid < 176) {
            const float4 wv = *(const float4 *)(Wc + tid * 4);
            const float4 cv = *(const float4 *)(tokbuf + 15 * TPITCH + tid * 4);
            float4 r;
            r.x = wv.x - cv.x; r.y = wv.y - cv.y;
            r.z = wv.z - cv.z; r.w = wv.w - cv.w;
            *(float4 *)(Wn + tid * 4) = r;
        }
        __syncthreads();
        cur ^= 1;
    }
}

// ---------------------------------------------------------------------------
// Final layernorm over DIM, in place on g_Y
// ---------------------------------------------------------------------------
__global__ __launch_bounds__(256) void ln_kernel(const float *__restrict__ pw,
                                                 const float *__restrict__ pb) {
    int row = blockIdx.x;
    int tid = threadIdx.x;
    float4 v = *((const float4 *)(g_Y + (size_t)row * 1024) + tid);
    float s1 = v.x + v.y + v.z + v.w;
    float s2 = v.x * v.x + v.y * v.y + v.z * v.z + v.w * v.w;
    wsum2(s1, s2);
    __shared__ float sa[8], sb[8];
    int w = tid >> 5, l = tid & 31;
    if (l == 0) { sa[w] = s1; sb[w] = s2; }
    __syncthreads();
    s1 = 0.f; s2 = 0.f;
#pragma unroll
    for (int i = 0; i < 8; i++) { s1 += sa[i]; s2 += sb[i]; }
    float mu = s1 * (1.f / 1024.f);
    float var = s2 * (1.f / 1024.f) - mu * mu;
    float rstd = rsqrtf(var + EPSV);
    float4 pwv = *((const float4 *)pw + tid);
    float4 pbv = *((const float4 *)pb + tid);
    float4 o;
    o.x = (v.x - mu) * rstd * pwv.x + pbv.x;
    o.y = (v.y - mu) * rstd * pwv.y + pbv.y;
    o.z = (v.z - mu) * rstd * pwv.z + pbv.z;
    o.w = (v.w - mu) * rstd * pwv.w + pbv.w;
    *((float4 *)(g_Y + (size_t)row * 1024) + tid) = o;
}

// ---------------------------------------------------------------------------
// Launch
// ---------------------------------------------------------------------------
extern "C" void kernel_launch(void *const *d_in, const int *in_sizes, int n_in,
                              void *d_out, int out_size) {
    const float *x     = (const float *)d_in[0];
    const float *posf  = (const float *)d_in[1];
    const float *Wq    = (const float *)d_in[2];
    const float *Wk    = (const float *)d_in[3];
    const float *Wv    = (const float *)d_in[4];
    const float *Wo    = (const float *)d_in[5];
    const float *lrW   = (const float *)d_in[6];
    const float *lrb   = (const float *)d_in[7];
    const float *gsc   = (const float *)d_in[8];
    const float *tgam  = (const float *)d_in[9];
    const float *tbet  = (const float *)d_in[10];
    const float *postw = (const float *)d_in[11];
    const float *postb = (const float *)d_in[12];
    const float *coeff = (const float *)d_in[13];
    const float *knots = (const float *)d_in[14];
    float *out = (float *)d_out;

    const int scan_smem = (MB * TPITCH + 2 * NB * HD) * sizeof(float);  // 54784 B
    cudaFuncSetAttribute(scan_kernel, cudaFuncAttributeMaxDynamicSharedMemorySize,
                         scan_smem);

    rope_tab_kernel<<<(SS * (HD / 2) + 1023) / 1024, 1024>>>(posf);
    tc_qkv_kernel<<<dim3(DIM / 128, BB * SS / 128, 3), 256>>>(x, Wq, Wk, Wv);
    eta_kernel<<<BB * SS, 128>>>(x, lrW, lrb, gsc);
    scan_kernel<<<BB * HH, 512, scan_smem>>>(tgam, tbet, knots, coeff);
    ln_kernel<<<BB * SS, 256>>>(postw, postb);
    tc_out_kernel<<<dim3(DIM / 128, BB * SS / 128, 1), 256>>>(Wo, out);
}

// round 14
// speedup vs baseline: 1.0616x; 1.0075x over previous
#include <cuda_runtime.h>
#include <cstdint>

// ---------------------------------------------------------------------------
// Problem constants
// ---------------------------------------------------------------------------
#define BB   4
#define SS   2048
#define DIM  1024
#define HH   16
#define HD   64
#define MB   16
#define NMB  128           // S / MB
#define NB   11            // CP + DEG
#define NKNOTS 15
#define EPSV 1e-6f
#define TPITCH 768         // 12 * 64 floats per m-block in tokbuf

// ---------------------------------------------------------------------------
// Device scratch (no cudaMalloc allowed)
// ---------------------------------------------------------------------------
__device__ float g_Q[(size_t)BB * HH * SS * HD];   // (b,h,s,d)
__device__ float g_K[(size_t)BB * HH * SS * HD];
__device__ float g_V[(size_t)BB * HH * SS * HD];
__device__ float g_Y[(size_t)BB * SS * DIM];       // (b,s,dim)
__device__ float g_eta[(size_t)BB * HH * NMB * MB];
__device__ float g_cos[SS * (HD / 2)];
__device__ float g_sin[SS * (HD / 2)];
__device__ float g_mu[(size_t)BB * SS];            // LN row stats
__device__ float g_rs[(size_t)BB * SS];

// ---------------------------------------------------------------------------
// Helpers
// ---------------------------------------------------------------------------
__device__ __forceinline__ void wsum2(float &a, float &b) {
#pragma unroll
    for (int o = 16; o > 0; o >>= 1) {
        a += __shfl_xor_sync(0xffffffffu, a, o);
        b += __shfl_xor_sync(0xffffffffu, b, o);
    }
}

__device__ __forceinline__ uint32_t f2tf32(float x) {
    uint32_t r;
    asm("cvt.rna.tf32.f32 %0, %1;" : "=r"(r) : "f"(x));
    return r;
}

__device__ __forceinline__ uint4 cvt4(uint4 v) {
    uint4 r;
    r.x = f2tf32(__uint_as_float(v.x));
    r.y = f2tf32(__uint_as_float(v.y));
    r.z = f2tf32(__uint_as_float(v.z));
    r.w = f2tf32(__uint_as_float(v.w));
    return r;
}

__device__ __forceinline__ void mma_tf32(float *d, const uint32_t *a,
                                         const uint32_t *b) {
    asm volatile(
        "mma.sync.aligned.m16n8k8.row.col.f32.tf32.tf32.f32 "
        "{%0,%1,%2,%3}, {%4,%5,%6,%7}, {%8,%9}, {%0,%1,%2,%3};\n"
        : "+f"(d[0]), "+f"(d[1]), "+f"(d[2]), "+f"(d[3])
        : "r"(a[0]), "r"(a[1]), "r"(a[2]), "r"(a[3]), "r"(b[0]), "r"(b[1]));
}

// Sparse uniform-knot cubic B-spline: at most 4 nonzero basis values.
__device__ __forceinline__ void bspline4(float x, float kn0, float inv_h,
                                         int &jbase, float (&w)[4]) {
    float u = (x - kn0) * inv_h;
    float fi = floorf(u);
    float t = u - fi;
    int idx = (int)fi;
    bool valid = (u >= 0.0f) && (u < 14.0f);
    float t2 = t * t, t3 = t2 * t;
    float omt = 1.0f - t;
    const float s = 1.0f / 6.0f;
    jbase = idx - 3;
    float w0 = omt * omt * omt * s;
    float w1 = fmaf(3.f, t3, fmaf(-6.f, t2, 4.f)) * s;
    float w2 = fmaf(-3.f, t3, fmaf(3.f, t2, fmaf(3.f, t, 1.f))) * s;
    float w3 = t3 * s;
    w[0] = (valid && jbase >= 0 && jbase <= 10) ? w0 : 0.f;
    w[1] = (valid && jbase + 1 >= 0 && jbase + 1 <= 10) ? w1 : 0.f;
    w[2] = (valid && jbase + 2 >= 0 && jbase + 2 <= 10) ? w2 : 0.f;
    w[3] = (valid && jbase + 3 <= 10) ? w3 : 0.f;
}

__device__ __forceinline__ int clampj(int j) {
    return j < 0 ? 0 : (j > 10 ? 10 : j);
}

// ---------------------------------------------------------------------------
// RoPE table: double-precision cos/sin of the fp32 angles
// ---------------------------------------------------------------------------
__global__ void rope_tab_kernel(const float *__restrict__ posf) {
    int i = blockIdx.x * blockDim.x + threadIdx.x;
    if (i < SS * (HD / 2)) {
        double a = (double)posf[i];
        g_cos[i] = (float)cos(a);
        g_sin[i] = (float)sin(a);
    }
}

// ---------------------------------------------------------------------------
// 1xTF32 tensor-core GEMM core (exact R7 winner: single buffer, 2 bars/tile)
// C(128x128) = A(128xK) * W(128xK)^T ; 256 thr = 8 warps 2(M)x4(N)
// ---------------------------------------------------------------------------
#define SPITCH 20   // smem row pitch (uint32) — 16B-aligned stores, conflict-free

__device__ __forceinline__ void tc_gemm_core(
    const float *__restrict__ A, const float *__restrict__ B,
    uint32_t *As, uint32_t *Bs,
    float (&acc)[4][4][4], int rowBase, int colBase) {
    int tid = threadIdx.x;
    int lane = tid & 31, wid = tid >> 5;
    int wm = wid >> 2, wn = wid & 3;
    int r0 = tid >> 2, c4 = (tid & 3) << 2;

    const uint4 *pA = (const uint4 *)(A + (size_t)(rowBase + r0) * 1024 + c4);
    const uint4 *pB = (const uint4 *)(B + (size_t)(colBase + r0) * 1024 + c4);
    const int rstep = 64 * 1024 / 4;   // +64 rows, in uint4 units

    uint4 va0 = pA[0], va1 = pA[rstep];
    uint4 vb0 = pB[0], vb1 = pB[rstep];

    for (int k0 = 0; k0 < 1024; k0 += 16) {
        __syncthreads();
        *(uint4 *)&As[r0 * SPITCH + c4] = cvt4(va0);
        *(uint4 *)&As[(r0 + 64) * SPITCH + c4] = cvt4(va1);
        *(uint4 *)&Bs[r0 * SPITCH + c4] = cvt4(vb0);
        *(uint4 *)&Bs[(r0 + 64) * SPITCH + c4] = cvt4(vb1);
        __syncthreads();
        if (k0 + 16 < 1024) {
            int ko = (k0 + 16) >> 2;
            va0 = pA[ko]; va1 = pA[ko + rstep];
            vb0 = pB[ko]; vb1 = pB[ko + rstep];
        }
#pragma unroll
        for (int ks = 0; ks < 2; ks++) {
            int kb = ks * 8 + (lane & 3);
            uint32_t ah[4][4], bh[4][2];
#pragma unroll
            for (int mt = 0; mt < 4; mt++) {
                int row = wm * 64 + mt * 16 + (lane >> 2);
                ah[mt][0] = As[row * SPITCH + kb];
                ah[mt][1] = As[(row + 8) * SPITCH + kb];
                ah[mt][2] = As[row * SPITCH + kb + 4];
                ah[mt][3] = As[(row + 8) * SPITCH + kb + 4];
            }
#pragma unroll
            for (int nt = 0; nt < 4; nt++) {
                int col = wn * 32 + nt * 8 + (lane >> 2);
                bh[nt][0] = Bs[col * SPITCH + kb];
                bh[nt][1] = Bs[col * SPITCH + kb + 4];
            }
#pragma unroll
            for (int mt = 0; mt < 4; mt++)
#pragma unroll
                for (int nt = 0; nt < 4; nt++)
                    mma_tf32(acc[mt][nt], ah[mt], bh[nt]);
        }
    }
}

// QKV projection + RoPE, scattering into (b,h,s,d) layout. blockIdx.z in {0,1,2}
__global__ __launch_bounds__(256) void tc_qkv_kernel(
    const float *__restrict__ x, const float *__restrict__ Wq,
    const float *__restrict__ Wk, const float *__restrict__ Wv) {
    __shared__ uint32_t As[128 * SPITCH], Bs[128 * SPITCH];
    const float *W = (blockIdx.z == 0) ? Wq : (blockIdx.z == 1) ? Wk : Wv;
    float *O = (blockIdx.z == 0) ? g_Q : (blockIdx.z == 1) ? g_K : g_V;

    float acc[4][4][4];
#pragma unroll
    for (int a = 0; a < 4; a++)
#pragma unroll
        for (int b = 0; b < 4; b++)
#pragma unroll
            for (int c = 0; c < 4; c++) acc[a][b][c] = 0.f;

    int rowBase = blockIdx.y * 128, colBase = blockIdx.x * 128;
    tc_gemm_core(x, W, As, Bs, acc, rowBase, colBase);

    int lane = threadIdx.x & 31, wid = threadIdx.x >> 5;
    int wm = wid >> 2, wn = wid & 3;
#pragma unroll
    for (int mt = 0; mt < 4; mt++) {
        int r = rowBase + wm * 64 + mt * 16 + (lane >> 2);
#pragma unroll
        for (int half = 0; half < 2; half++) {
            int ri = r + half * 8;
            int b = ri >> 11;  // S = 2048
            int s = ri & 2047;
#pragma unroll
            for (int nt = 0; nt < 4; nt++) {
                int c = colBase + wn * 32 + nt * 8 + 2 * (lane & 3);
                int h = c >> 6;
                int dd = c & 63;
                int jj = dd >> 1;
                float cs = g_cos[s * 32 + jj];
                float sn = g_sin[s * 32 + jj];
                float t1 = acc[mt][nt][2 * half];
                float t2 = acc[mt][nt][2 * half + 1];
                size_t o = (((size_t)(b * HH + h) * SS) + s) * HD + dd;
                O[o]     = t1 * cs - t2 * sn;
                O[o + 1] = t1 * sn + t2 * cs;
            }
        }
    }
}

// ---------------------------------------------------------------------------
// LN-fused out-projection core: stages A as LN(g_Y) = (v-mu)*rstd*pw+pb,
// tf32-rounded. Identical mma structure to tc_gemm_core.
// ---------------------------------------------------------------------------
__device__ __forceinline__ uint4 cvt4ln(float4 v, float mu, float rstd,
                                        float4 pw4, float4 pb4) {
    uint4 r;
    r.x = f2tf32((v.x - mu) * rstd * pw4.x + pb4.x);
    r.y = f2tf32((v.y - mu) * rstd * pw4.y + pb4.y);
    r.z = f2tf32((v.z - mu) * rstd * pw4.z + pb4.z);
    r.w = f2tf32((v.w - mu) * rstd * pw4.w + pb4.w);
    return r;
}

__global__ __launch_bounds__(256) void tc_out_kernel(
    const float *__restrict__ Wo, const float *__restrict__ pw,
    const float *__restrict__ pb, float *__restrict__ out) {
    __shared__ uint32_t As[128 * SPITCH], Bs[128 * SPITCH];
    float acc[4][4][4];
#pragma unroll
    for (int a = 0; a < 4; a++)
#pragma unroll
        for (int b = 0; b < 4; b++)
#pragma unroll
            for (int c = 0; c < 4; c++) acc[a][b][c] = 0.f;

    int tid = threadIdx.x;
    int lane = tid & 31, wid = tid >> 5;
    int wm = wid >> 2, wn = wid & 3;
    int r0 = tid >> 2, c4 = (tid & 3) << 2;
    int rowBase = blockIdx.y * 128, colBase = blockIdx.x * 128;

    const float4 *pA = (const float4 *)(g_Y + (size_t)(rowBase + r0) * 1024 + c4);
    const uint4 *pB = (const uint4 *)((const uint32_t *)Wo +
                                      (size_t)(colBase + r0) * 1024 + c4);
    const int rstep = 64 * 1024 / 4;

    float mu0 = g_mu[rowBase + r0], rs0 = g_rs[rowBase + r0];
    float mu1 = g_mu[rowBase + r0 + 64], rs1 = g_rs[rowBase + r0 + 64];

    float4 va0 = pA[0], va1 = pA[rstep];
    uint4 vb0 = pB[0], vb1 = pB[rstep];
    float4 pw4 = *(const float4 *)(pw + c4);
    float4 pb4 = *(const float4 *)(pb + c4);

    for (int k0 = 0; k0 < 1024; k0 += 16) {
        __syncthreads();
        *(uint4 *)&As[r0 * SPITCH + c4] = cvt4ln(va0, mu0, rs0, pw4, pb4);
        *(uint4 *)&As[(r0 + 64) * SPITCH + c4] = cvt4ln(va1, mu1, rs1, pw4, pb4);
        *(uint4 *)&Bs[r0 * SPITCH + c4] = cvt4(vb0);
        *(uint4 *)&Bs[(r0 + 64) * SPITCH + c4] = cvt4(vb1);
        __syncthreads();
        if (k0 + 16 < 1024) {
            int ko = (k0 + 16) >> 2;
            va0 = pA[ko]; va1 = pA[ko + rstep];
            vb0 = pB[ko]; vb1 = pB[ko + rstep];
            pw4 = *(const float4 *)(pw + k0 + 16 + c4);
            pb4 = *(const float4 *)(pb + k0 + 16 + c4);
        }
#pragma unroll
        for (int ks = 0; ks < 2; ks++) {
            int kb = ks * 8 + (lane & 3);
            uint32_t ah[4][4], bh[4][2];
#pragma unroll
            for (int mt = 0; mt < 4; mt++) {
                int row = wm * 64 + mt * 16 + (lane >> 2);
                ah[mt][0] = As[row * SPITCH + kb];
                ah[mt][1] = As[(row + 8) * SPITCH + kb];
                ah[mt][2] = As[row * SPITCH + kb + 4];
                ah[mt][3] = As[(row + 8) * SPITCH + kb + 4];
            }
#pragma unroll
            for (int nt = 0; nt < 4; nt++) {
                int col = wn * 32 + nt * 8 + (lane >> 2);
                bh[nt][0] = Bs[col * SPITCH + kb];
                bh[nt][1] = Bs[col * SPITCH + kb + 4];
            }
#pragma unroll
            for (int mt = 0; mt < 4; mt++)
#pragma unroll
                for (int nt = 0; nt < 4; nt++)
                    mma_tf32(acc[mt][nt], ah[mt], bh[nt]);
        }
    }

#pragma unroll
    for (int mt = 0; mt < 4; mt++) {
        int r = rowBase + wm * 64 + mt * 16 + (lane >> 2);
#pragma unroll
        for (int half = 0; half < 2; half++) {
            size_t ri = r + half * 8;
#pragma unroll
            for (int nt = 0; nt < 4; nt++) {
                int c = colBase + wn * 32 + nt * 8 + 2 * (lane & 3);
                float2 v = make_float2(acc[mt][nt][2 * half],
                                       acc[mt][nt][2 * half + 1]);
                *(float2 *)(out + ri * 1024 + c) = v;
            }
        }
    }
}

// ---------------------------------------------------------------------------
// eta = sigmoid(x . lr_W[h] + lr_b[h]) / HD * gs[m]
// ---------------------------------------------------------------------------
__global__ __launch_bounds__(128) void eta_kernel(
    const float *__restrict__ x, const float *__restrict__ lrW,
    const float *__restrict__ lrb, const float *__restrict__ gsc) {
    int row = blockIdx.x;  // b*2048 + s
    __shared__ float xs[1024];
    const float4 *xp = (const float4 *)(x + (size_t)row * 1024);
    float4 *xsp = (float4 *)xs;
    xsp[threadIdx.x] = xp[threadIdx.x];
    xsp[threadIdx.x + 128] = xp[threadIdx.x + 128];
    __syncthreads();

    int w = threadIdx.x >> 5, l = threadIdx.x & 31;
    int b = row >> 11, s = row & 2047;
    int n = s >> 4, m = s & 15;
    float gs = fmaxf(1.0f / (float)(m + 1) + gsc[m], 0.0f);

#pragma unroll
    for (int hh = 0; hh < 4; hh++) {
        int h = w * 4 + hh;
        const float *wp = lrW + (size_t)h * 1024;
        float sum = 0.f;
        for (int k = l; k < 1024; k += 32) sum = fmaf(xs[k], wp[k], sum);
#pragma unroll
        for (int o = 16; o > 0; o >>= 1) sum += __shfl_xor_sync(0xffffffffu, sum, o);
        if (l == 0) {
            float lr = 1.0f / (1.0f + __expf(-(sum + lrb[h]))) * (1.0f / 64.0f);
            g_eta[(((size_t)b * HH + h) * NMB + n) * MB + m] = lr * gs;
        }
    }
}

// ---------------------------------------------------------------------------
// Sequential TTT scan (R11 version: register-batched cumsum)
// ---------------------------------------------------------------------------
__global__ __launch_bounds__(512) void scan_kernel(
    const float *__restrict__ gamma, const float *__restrict__ beta,
    const float *__restrict__ knots, const float *__restrict__ coeff) {
    extern __shared__ float sm[];
    float *tokbuf = sm;                       // [MB][12][HD]
    float *Wsbuf = sm + MB * TPITCH;          // [2][NB*HD]

    int bh = blockIdx.x;
    int b = bh >> 4, h = bh & 15;
    int tid = threadIdx.x, m = tid >> 5, l = tid & 31;

    float kn0 = knots[0];
    float kn14 = knots[NKNOTS - 1];
    float inv_h = 14.0f / (kn14 - kn0);

    float g0 = gamma[h * HD + l], g1 = gamma[h * HD + l + 32];
    float be0 = beta[h * HD + l], be1 = beta[h * HD + l + 32];

    for (int idx = tid; idx < NB * HD; idx += 512)
        Wsbuf[idx] = coeff[(size_t)h * NB * HD + idx];

    const float *Qb = g_Q + (size_t)bh * SS * HD;
    const float *Kb = g_K + (size_t)bh * SS * HD;
    const float *Vb = g_V + (size_t)bh * SS * HD;
    const float *eb = g_eta + (size_t)bh * NMB * MB;
    float *Yb = g_Y + (size_t)b * SS * DIM + h * HD;

    float *cbase = tokbuf + (tid >> 4) * HD + ((tid & 15) << 2);
    float *mb = tokbuf + m * TPITCH;

    int cur = 0;
    __syncthreads();

    int base0 = m * HD + l;
    float q0 = Qb[base0], q1 = Qb[base0 + 32];
    float k0 = Kb[base0], k1 = Kb[base0 + 32];
    float v0 = Vb[base0], v1 = Vb[base0 + 32];
    float e  = eb[m];

    for (int n = 0; n < NMB; n++) {
        float cq0 = q0, cq1 = q1, ck0 = k0, ck1 = k1, cv0 = v0, cv1 = v1, ce = e;
        int np = (n + 1 < NMB) ? n + 1 : n;
        int basen = (np * MB + m) * HD + l;
        q0 = Qb[basen]; q1 = Qb[basen + 32];
        k0 = Kb[basen]; k1 = Kb[basen + 32];
        v0 = Vb[basen]; v1 = Vb[basen + 32];
        e  = eb[np * MB + m];

        const float *Wc = Wsbuf + cur * (NB * HD);
        float *Wn = Wsbuf + (cur ^ 1) * (NB * HD);

        int jk0, jk1;
        float wk0[4], wk1[4];
        bspline4(ck0, kn0, inv_h, jk0, wk0);
        bspline4(ck1, kn0, inv_h, jk1, wk1);

        float z0 = __fdividef(ck0, 1.0f + __expf(-ck0));
        float z1 = __fdividef(ck1, 1.0f + __expf(-ck1));
#pragma unroll
        for (int k = 0; k < 4; k++) {
            z0 = fmaf(wk0[k], Wc[clampj(jk0 + k) * HD + l], z0);
            z1 = fmaf(wk1[k], Wc[clampj(jk1 + k) * HD + l + 32], z1);
        }
        float s1 = z0 + z1, s2 = fmaf(z0, z0, z1 * z1);
        wsum2(s1, s2);
        float mu = s1 * (1.f / 64.f);
        float var = s2 * (1.f / 64.f) - mu * mu;
        float rstd = rsqrtf(var + EPSV);
        float xh0 = (z0 - mu) * rstd, xh1 = (z1 - mu) * rstd;
        float gh0 = (fmaf(g0, xh0, be0) - (cv0 - ck0)) * g0;
        float gh1 = (fmaf(g1, xh1, be1) - (cv1 - ck1)) * g1;
        s1 = gh0 + gh1;
        s2 = fmaf(gh0, xh0, gh1 * xh1);
        wsum2(s1, s2);
        float mg = s1 * (1.f / 64.f), mgx = s2 * (1.f / 64.f);
        float eg0 = ce * (gh0 - mg - xh0 * mgx) * rstd;
        float eg1 = ce * (gh1 - mg - xh1 * mgx) * rstd;

        float4 z4 = make_float4(0.f, 0.f, 0.f, 0.f);
#pragma unroll
        for (int i = 0; i < 6; i++)
            ((float4 *)mb)[i * 32 + l] = z4;
        __syncwarp();
#pragma unroll
        for (int k = 0; k < 4; k++) {
            if (wk0[k] != 0.f) mb[(jk0 + k) * HD + l] = eg0 * wk0[k];
            if (wk1[k] != 0.f) mb[(jk1 + k) * HD + l + 32] = eg1 * wk1[k];
        }
        __syncthreads();

        // ---- phase B: cumsum over m, register-batched (2 x 8) ----
        if (tid < 176) {
            float4 vv[8];
            float4 carry = make_float4(0.f, 0.f, 0.f, 0.f);
#pragma unroll
            for (int blk = 0; blk < 2; blk++) {
                float *p = cbase + blk * 8 * TPITCH;
#pragma unroll
                for (int mm = 0; mm < 8; mm++)
                    vv[mm] = *(float4 *)(p + mm * TPITCH);
                vv[0].x += carry.x; vv[0].y += carry.y;
                vv[0].z += carry.z; vv[0].w += carry.w;
#pragma unroll
                for (int mm = 1; mm < 8; mm++) {
                    vv[mm].x += vv[mm - 1].x; vv[mm].y += vv[mm - 1].y;
                    vv[mm].z += vv[mm - 1].z; vv[mm].w += vv[mm - 1].w;
                }
#pragma unroll
                for (int mm = 0; mm < 8; mm++)
                    *(float4 *)(p + mm * TPITCH) = vv[mm];
                carry = vv[7];
            }
        }
        __syncthreads();

        int jq0, jq1;
        float wq0[4], wq1[4];
        bspline4(cq0, kn0, inv_h, jq0, wq0);
        bspline4(cq1, kn0, inv_h, jq1, wq1);
        float zq0 = __fdividef(cq0, 1.0f + __expf(-cq0));
        float zq1 = __fdividef(cq1, 1.0f + __expf(-cq1));
#pragma unroll
        for (int k = 0; k < 4; k++) {
            int ja = clampj(jq0 + k) * HD + l;
            int jb = clampj(jq1 + k) * HD + l + 32;
            zq0 = fmaf(wq0[k], Wc[ja] - mb[ja], zq0);
            zq1 = fmaf(wq1[k], Wc[jb] - mb[jb], zq1);
        }
        s1 = zq0 + zq1;
        s2 = fmaf(zq0, zq0, zq1 * zq1);
        wsum2(s1, s2);
        mu = s1 * (1.f / 64.f);
        var = s2 * (1.f / 64.f) - mu * mu;
        rstd = rsqrtf(var + EPSV);
        float y0 = cq0 + fmaf(g0, (zq0 - mu) * rstd, be0);
        float y1 = cq1 + fmaf(g1, (zq1 - mu) * rstd, be1);

        size_t yo = (size_t)(n * MB + m) * DIM;
        Yb[yo + l] = y0;
        Yb[yo + l + 32] = y1;

        if (tid < 176) {
            const float4 wv = *(const float4 *)(Wc + tid * 4);
            const float4 cv = *(const float4 *)(tokbuf + 15 * TPITCH + tid * 4);
            float4 r;
            r.x = wv.x - cv.x; r.y = wv.y - cv.y;
            r.z = wv.z - cv.z; r.w = wv.w - cv.w;
            *(float4 *)(Wn + tid * 4) = r;
        }
        __syncthreads();
        cur ^= 1;
    }
}

// ---------------------------------------------------------------------------
// LN row stats only (mu, rstd per row); apply is fused into tc_out staging
// ---------------------------------------------------------------------------
__global__ __launch_bounds__(256) void ln_stats_kernel() {
    int row = blockIdx.x;
    int tid = threadIdx.x;
    float4 v = *((const float4 *)(g_Y + (size_t)row * 1024) + tid);
    float s1 = v.x + v.y + v.z + v.w;
    float s2 = v.x * v.x + v.y * v.y + v.z * v.z + v.w * v.w;
    wsum2(s1, s2);
    __shared__ float sa[8], sb[8];
    int w = tid >> 5, l = tid & 31;
    if (l == 0) { sa[w] = s1; sb[w] = s2; }
    __syncthreads();
    if (tid == 0) {
        s1 = 0.f; s2 = 0.f;
#pragma unroll
        for (int i = 0; i < 8; i++) { s1 += sa[i]; s2 += sb[i]; }
        float mu = s1 * (1.f / 1024.f);
        float var = s2 * (1.f / 1024.f) - mu * mu;
        g_mu[row] = mu;
        g_rs[row] = rsqrtf(var + EPSV);
    }
}

// ---------------------------------------------------------------------------
// Launch
// ---------------------------------------------------------------------------
extern "C" void kernel_launch(void *const *d_in, const int *in_sizes, int n_in,
                              void *d_out, int out_size) {
    const float *x     = (const float *)d_in[0];
    const float *posf  = (const float *)d_in[1];
    const float *Wq    = (const float *)d_in[2];
    const float *Wk    = (const float *)d_in[3];
    const float *Wv    = (const float *)d_in[4];
    const float *Wo    = (const float *)d_in[5];
    const float *lrW   = (const float *)d_in[6];
    const float *lrb   = (const float *)d_in[7];
    const float *gsc   = (const float *)d_in[8];
    const float *tgam  = (const float *)d_in[9];
    const float *tbet  = (const float *)d_in[10];
    const float *postw = (const float *)d_in[11];
    const float *postb = (const float *)d_in[12];
    const float *coeff = (const float *)d_in[13];
    const float *knots = (const float *)d_in[14];
    float *out = (float *)d_out;

    const int scan_smem = (MB * TPITCH + 2 * NB * HD) * sizeof(float);  // 54784 B
    cudaFuncSetAttribute(scan_kernel, cudaFuncAttributeMaxDynamicSharedMemorySize,
                         scan_smem);

    rope_tab_kernel<<<(SS * (HD / 2) + 1023) / 1024, 1024>>>(posf);
    tc_qkv_kernel<<<dim3(DIM / 128, BB * SS / 128, 3), 256>>>(x, Wq, Wk, Wv);
    eta_kernel<<<BB * SS, 128>>>(x, lrW, lrb, gsc);
    scan_kernel<<<BB * HH, 512, scan_smem>>>(tgam, tbet, knots, coeff);
    ln_stats_kernel<<<BB * SS, 256>>>();
    tc_out_kernel<<<dim3(DIM / 128, BB * SS / 128, 1), 256>>>(Wo, postw, postb, out);
}

// round 16
// speedup vs baseline: 1.2229x; 1.1520x over previous
#include <cuda_runtime.h>
#include <cstdint>

// ---------------------------------------------------------------------------
// Problem constants
// ---------------------------------------------------------------------------
#define BB   4
#define SS   2048
#define DIM  1024
#define HH   16
#define HD   64
#define MB   16
#define NMB  128           // S / MB
#define NB   11            // CP + DEG
#define NKNOTS 15
#define EPSV 1e-6f
#define TPITCH 768         // 12 * 64 floats per m-block in tokbuf

// ---------------------------------------------------------------------------
// Device scratch (no cudaMalloc allowed)
// ---------------------------------------------------------------------------
__device__ float g_Q[(size_t)BB * HH * SS * HD];   // (b,h,s,d)
__device__ float g_K[(size_t)BB * HH * SS * HD];
__device__ float g_V[(size_t)BB * HH * SS * HD];
__device__ float g_Y[(size_t)BB * SS * DIM];       // (b,s,dim)
__device__ float g_eta[(size_t)BB * HH * NMB * MB];
__device__ float g_cos[SS * (HD / 2)];
__device__ float g_sin[SS * (HD / 2)];
__device__ float g_mu[(size_t)BB * SS];            // LN row stats
__device__ float g_rs[(size_t)BB * SS];

// ---------------------------------------------------------------------------
// Helpers
// ---------------------------------------------------------------------------
__device__ __forceinline__ void wsum2(float &a, float &b) {
#pragma unroll
    for (int o = 16; o > 0; o >>= 1) {
        a += __shfl_xor_sync(0xffffffffu, a, o);
        b += __shfl_xor_sync(0xffffffffu, b, o);
    }
}

__device__ __forceinline__ uint32_t f2tf32(float x) {
    uint32_t r;
    asm("cvt.rna.tf32.f32 %0, %1;" : "=r"(r) : "f"(x));
    return r;
}

__device__ __forceinline__ uint4 cvt4(uint4 v) {
    uint4 r;
    r.x = f2tf32(__uint_as_float(v.x));
    r.y = f2tf32(__uint_as_float(v.y));
    r.z = f2tf32(__uint_as_float(v.z));
    r.w = f2tf32(__uint_as_float(v.w));
    return r;
}

// pack two f32 -> f16x2 (lo = first arg)
__device__ __forceinline__ uint32_t pack_h2(float lo, float hi) {
    uint32_t r;
    asm("cvt.rn.f16x2.f32 %0, %1, %2;" : "=r"(r) : "f"(hi), "f"(lo));
    return r;
}

__device__ __forceinline__ void mma_tf32(float *d, const uint32_t *a,
                                         const uint32_t *b) {
    asm volatile(
        "mma.sync.aligned.m16n8k8.row.col.f32.tf32.tf32.f32 "
        "{%0,%1,%2,%3}, {%4,%5,%6,%7}, {%8,%9}, {%0,%1,%2,%3};\n"
        : "+f"(d[0]), "+f"(d[1]), "+f"(d[2]), "+f"(d[3])
        : "r"(a[0]), "r"(a[1]), "r"(a[2]), "r"(a[3]), "r"(b[0]), "r"(b[1]));
}

__device__ __forceinline__ void mma_f16(float *d, const uint32_t *a,
                                        const uint32_t *b) {
    asm volatile(
        "mma.sync.aligned.m16n8k16.row.col.f32.f16.f16.f32 "
        "{%0,%1,%2,%3}, {%4,%5,%6,%7}, {%8,%9}, {%0,%1,%2,%3};\n"
        : "+f"(d[0]), "+f"(d[1]), "+f"(d[2]), "+f"(d[3])
        : "r"(a[0]), "r"(a[1]), "r"(a[2]), "r"(a[3]), "r"(b[0]), "r"(b[1]));
}

// Sparse uniform-knot cubic B-spline: at most 4 nonzero basis values.
__device__ __forceinline__ void bspline4(float x, float kn0, float inv_h,
                                         int &jbase, float (&w)[4]) {
    float u = (x - kn0) * inv_h;
    float fi = floorf(u);
    float t = u - fi;
    int idx = (int)fi;
    bool valid = (u >= 0.0f) && (u < 14.0f);
    float t2 = t * t, t3 = t2 * t;
    float omt = 1.0f - t;
    const float s = 1.0f / 6.0f;
    jbase = idx - 3;
    float w0 = omt * omt * omt * s;
    float w1 = fmaf(3.f, t3, fmaf(-6.f, t2, 4.f)) * s;
    float w2 = fmaf(-3.f, t3, fmaf(3.f, t2, fmaf(3.f, t, 1.f))) * s;
    float w3 = t3 * s;
    w[0] = (valid && jbase >= 0 && jbase <= 10) ? w0 : 0.f;
    w[1] = (valid && jbase + 1 >= 0 && jbase + 1 <= 10) ? w1 : 0.f;
    w[2] = (valid && jbase + 2 >= 0 && jbase + 2 <= 10) ? w2 : 0.f;
    w[3] = (valid && jbase + 3 <= 10) ? w3 : 0.f;
}

__device__ __forceinline__ int clampj(int j) {
    return j < 0 ? 0 : (j > 10 ? 10 : j);
}

// ---------------------------------------------------------------------------
// RoPE table
// ---------------------------------------------------------------------------
__global__ void rope_tab_kernel(const float *__restrict__ posf) {
    int i = blockIdx.x * blockDim.x + threadIdx.x;
    if (i < SS * (HD / 2)) {
        double a = (double)posf[i];
        g_cos[i] = (float)cos(a);
        g_sin[i] = (float)sin(a);
    }
}

// ---------------------------------------------------------------------------
// FP16 m16n8k16 GEMM core for QKV: C(128x128)=A(128xK)*W(128xK)^T
// smem rows: 12 u32 (8 f16x2 pairs + pad 4) — fragment LDS bank-disjoint.
// 256 thr = 8 warps 2(M)x4(N); 16 mma per 16-K tile (half of tf32 count).
// ---------------------------------------------------------------------------
#define HPITCH 12

__device__ __forceinline__ void h_gemm_core(
    const float *__restrict__ A, const float *__restrict__ B,
    uint32_t *As, uint32_t *Bs,
    float (&acc)[4][4][4], int rowBase, int colBase) {
    int tid = threadIdx.x;
    int lane = tid & 31, wid = tid >> 5;
    int wm = wid >> 2, wn = wid & 3;
    int r0 = tid >> 2, c4 = (tid & 3) << 2;   // 4 consecutive floats
    int p0 = (tid & 3) << 1;                  // u32 pair index (even)

    const float4 *pA = (const float4 *)(A + (size_t)(rowBase + r0) * 1024 + c4);
    const float4 *pB = (const float4 *)(B + (size_t)(colBase + r0) * 1024 + c4);
    const int rstep = 64 * 1024 / 4;   // +64 rows, in float4 units

    float4 va0 = pA[0], va1 = pA[rstep];
    float4 vb0 = pB[0], vb1 = pB[rstep];

    for (int k0 = 0; k0 < 1024; k0 += 16) {
        __syncthreads();
        *(uint2 *)&As[r0 * HPITCH + p0] =
            make_uint2(pack_h2(va0.x, va0.y), pack_h2(va0.z, va0.w));
        *(uint2 *)&As[(r0 + 64) * HPITCH + p0] =
            make_uint2(pack_h2(va1.x, va1.y), pack_h2(va1.z, va1.w));
        *(uint2 *)&Bs[r0 * HPITCH + p0] =
            make_uint2(pack_h2(vb0.x, vb0.y), pack_h2(vb0.z, vb0.w));
        *(uint2 *)&Bs[(r0 + 64) * HPITCH + p0] =
            make_uint2(pack_h2(vb1.x, vb1.y), pack_h2(vb1.z, vb1.w));
        __syncthreads();
        if (k0 + 16 < 1024) {
            int ko = (k0 + 16) >> 2;
            va0 = pA[ko]; va1 = pA[ko + rstep];
            vb0 = pB[ko]; vb1 = pB[ko + rstep];
        }
        int q = lane & 3, rw = lane >> 2;
        uint32_t ah[4][4], bh[4][2];
#pragma unroll
        for (int mt = 0; mt < 4; mt++) {
            int row = wm * 64 + mt * 16 + rw;
            ah[mt][0] = As[row * HPITCH + q];
            ah[mt][1] = As[(row + 8) * HPITCH + q];
            ah[mt][2] = As[row * HPITCH + q + 4];
            ah[mt][3] = As[(row + 8) * HPITCH + q + 4];
        }
#pragma unroll
        for (int nt = 0; nt < 4; nt++) {
            int col = wn * 32 + nt * 8 + rw;
            bh[nt][0] = Bs[col * HPITCH + q];
            bh[nt][1] = Bs[col * HPITCH + q + 4];
        }
#pragma unroll
        for (int mt = 0; mt < 4; mt++)
#pragma unroll
            for (int nt = 0; nt < 4; nt++)
                mma_f16(acc[mt][nt], ah[mt], bh[nt]);
    }
}

// QKV projection (fp16 core) + RoPE epilogue. blockIdx.z in {0,1,2}
__global__ __launch_bounds__(256) void tc_qkv_kernel(
    const float *__restrict__ x, const float *__restrict__ Wq,
    const float *__restrict__ Wk, const float *__restrict__ Wv) {
    __shared__ uint32_t As[128 * HPITCH], Bs[128 * HPITCH];
    const float *W = (blockIdx.z == 0) ? Wq : (blockIdx.z == 1) ? Wk : Wv;
    float *O = (blockIdx.z == 0) ? g_Q : (blockIdx.z == 1) ? g_K : g_V;

    float acc[4][4][4];
#pragma unroll
    for (int a = 0; a < 4; a++)
#pragma unroll
        for (int b = 0; b < 4; b++)
#pragma unroll
            for (int c = 0; c < 4; c++) acc[a][b][c] = 0.f;

    int rowBase = blockIdx.y * 128, colBase = blockIdx.x * 128;
    h_gemm_core(x, W, As, Bs, acc, rowBase, colBase);

    int lane = threadIdx.x & 31, wid = threadIdx.x >> 5;
    int wm = wid >> 2, wn = wid & 3;
#pragma unroll
    for (int mt = 0; mt < 4; mt++) {
        int r = rowBase + wm * 64 + mt * 16 + (lane >> 2);
#pragma unroll
        for (int half = 0; half < 2; half++) {
            int ri = r + half * 8;
            int b = ri >> 11;  // S = 2048
            int s = ri & 2047;
#pragma unroll
            for (int nt = 0; nt < 4; nt++) {
                int c = colBase + wn * 32 + nt * 8 + 2 * (lane & 3);
                int h = c >> 6;
                int dd = c & 63;
                int jj = dd >> 1;
                float cs = g_cos[s * 32 + jj];
                float sn = g_sin[s * 32 + jj];
                float t1 = acc[mt][nt][2 * half];
                float t2 = acc[mt][nt][2 * half + 1];
                size_t o = (((size_t)(b * HH + h) * SS) + s) * HD + dd;
                O[o]     = t1 * cs - t2 * sn;
                O[o + 1] = t1 * sn + t2 * cs;
            }
        }
    }
}

// ---------------------------------------------------------------------------
// LN-fused out-projection (tf32, R14 winner — kept for accuracy headroom)
// ---------------------------------------------------------------------------
#define SPITCH 20

__device__ __forceinline__ uint4 cvt4ln(float4 v, float mu, float rstd,
                                        float4 pw4, float4 pb4) {
    uint4 r;
    r.x = f2tf32((v.x - mu) * rstd * pw4.x + pb4.x);
    r.y = f2tf32((v.y - mu) * rstd * pw4.y + pb4.y);
    r.z = f2tf32((v.z - mu) * rstd * pw4.z + pb4.z);
    r.w = f2tf32((v.w - mu) * rstd * pw4.w + pb4.w);
    return r;
}

__global__ __launch_bounds__(256) void tc_out_kernel(
    const float *__restrict__ Wo, const float *__restrict__ pw,
    const float *__restrict__ pb, float *__restrict__ out) {
    __shared__ uint32_t As[128 * SPITCH], Bs[128 * SPITCH];
    float acc[4][4][4];
#pragma unroll
    for (int a = 0; a < 4; a++)
#pragma unroll
        for (int b = 0; b < 4; b++)
#pragma unroll
            for (int c = 0; c < 4; c++) acc[a][b][c] = 0.f;

    int tid = threadIdx.x;
    int lane = tid & 31, wid = tid >> 5;
    int wm = wid >> 2, wn = wid & 3;
    int r0 = tid >> 2, c4 = (tid & 3) << 2;
    int rowBase = blockIdx.y * 128, colBase = blockIdx.x * 128;

    const float4 *pA = (const float4 *)(g_Y + (size_t)(rowBase + r0) * 1024 + c4);
    const uint4 *pB = (const uint4 *)((const uint32_t *)Wo +
                                      (size_t)(colBase + r0) * 1024 + c4);
    const int rstep = 64 * 1024 / 4;

    float mu0 = g_mu[rowBase + r0], rs0 = g_rs[rowBase + r0];
    float mu1 = g_mu[rowBase + r0 + 64], rs1 = g_rs[rowBase + r0 + 64];

    float4 va0 = pA[0], va1 = pA[rstep];
    uint4 vb0 = pB[0], vb1 = pB[rstep];
    float4 pw4 = *(const float4 *)(pw + c4);
    float4 pb4 = *(const float4 *)(pb + c4);

    for (int k0 = 0; k0 < 1024; k0 += 16) {
        __syncthreads();
        *(uint4 *)&As[r0 * SPITCH + c4] = cvt4ln(va0, mu0, rs0, pw4, pb4);
        *(uint4 *)&As[(r0 + 64) * SPITCH + c4] = cvt4ln(va1, mu1, rs1, pw4, pb4);
        *(uint4 *)&Bs[r0 * SPITCH + c4] = cvt4(vb0);
        *(uint4 *)&Bs[(r0 + 64) * SPITCH + c4] = cvt4(vb1);
        __syncthreads();
        if (k0 + 16 < 1024) {
            int ko = (k0 + 16) >> 2;
            va0 = pA[ko]; va1 = pA[ko + rstep];
            vb0 = pB[ko]; vb1 = pB[ko + rstep];
            pw4 = *(const float4 *)(pw + k0 + 16 + c4);
            pb4 = *(const float4 *)(pb + k0 + 16 + c4);
        }
#pragma unroll
        for (int ks = 0; ks < 2; ks++) {
            int kb = ks * 8 + (lane & 3);
            uint32_t ah[4][4], bh[4][2];
#pragma unroll
            for (int mt = 0; mt < 4; mt++) {
                int row = wm * 64 + mt * 16 + (lane >> 2);
                ah[mt][0] = As[row * SPITCH + kb];
                ah[mt][1] = As[(row + 8) * SPITCH + kb];
                ah[mt][2] = As[row * SPITCH + kb + 4];
                ah[mt][3] = As[(row + 8) * SPITCH + kb + 4];
            }
#pragma unroll
            for (int nt = 0; nt < 4; nt++) {
                int col = wn * 32 + nt * 8 + (lane >> 2);
                bh[nt][0] = Bs[col * SPITCH + kb];
                bh[nt][1] = Bs[col * SPITCH + kb + 4];
            }
#pragma unroll
            for (int mt = 0; mt < 4; mt++)
#pragma unroll
                for (int nt = 0; nt < 4; nt++)
                    mma_tf32(acc[mt][nt], ah[mt], bh[nt]);
        }
    }

#pragma unroll
    for (int mt = 0; mt < 4; mt++) {
        int r = rowBase + wm * 64 + mt * 16 + (lane >> 2);
#pragma unroll
        for (int half = 0; half < 2; half++) {
            size_t ri = r + half * 8;
#pragma unroll
            for (int nt = 0; nt < 4; nt++) {
                int c = colBase + wn * 32 + nt * 8 + 2 * (lane & 3);
                float2 v = make_float2(acc[mt][nt][2 * half],
                                       acc[mt][nt][2 * half + 1]);
                *(float2 *)(out + ri * 1024 + c) = v;
            }
        }
    }
}

// ---------------------------------------------------------------------------
// eta = sigmoid(x . lr_W[h] + lr_b[h]) / HD * gs[m]
// ---------------------------------------------------------------------------
__global__ __launch_bounds__(128) void eta_kernel(
    const float *__restrict__ x, const float *__restrict__ lrW,
    const float *__restrict__ lrb, const float *__restrict__ gsc) {
    int row = blockIdx.x;  // b*2048 + s
    __shared__ float xs[1024];
    const float4 *xp = (const float4 *)(x + (size_t)row * 1024);
    float4 *xsp = (float4 *)xs;
    xsp[threadIdx.x] = xp[threadIdx.x];
    xsp[threadIdx.x + 128] = xp[threadIdx.x + 128];
    __syncthreads();

    int w = threadIdx.x >> 5, l = threadIdx.x & 31;
    int b = row >> 11, s = row & 2047;
    int n = s >> 4, m = s & 15;
    float gs = fmaxf(1.0f / (float)(m + 1) + gsc[m], 0.0f);

#pragma unroll
    for (int hh = 0; hh < 4; hh++) {
        int h = w * 4 + hh;
        const float *wp = lrW + (size_t)h * 1024;
        float sum = 0.f;
        for (int k = l; k < 1024; k += 32) sum = fmaf(xs[k], wp[k], sum);
#pragma unroll
        for (int o = 16; o > 0; o >>= 1) sum += __shfl_xor_sync(0xffffffffu, sum, o);
        if (l == 0) {
            float lr = 1.0f / (1.0f + __expf(-(sum + lrb[h]))) * (1.0f / 64.0f);
            g_eta[(((size_t)b * HH + h) * NMB + n) * MB + m] = lr * gs;
        }
    }
}

// ---------------------------------------------------------------------------
// Sequential TTT scan (R11/R13 winner: register-batched cumsum)
// ---------------------------------------------------------------------------
__global__ __launch_bounds__(512) void scan_kernel(
    const float *__restrict__ gamma, const float *__restrict__ beta,
    const float *__restrict__ knots, const float *__restrict__ coeff) {
    extern __shared__ float sm[];
    float *tokbuf = sm;                       // [MB][12][HD]
    float *Wsbuf = sm + MB * TPITCH;          // [2][NB*HD]

    int bh = blockIdx.x;
    int b = bh >> 4, h = bh & 15;
    int tid = threadIdx.x, m = tid >> 5, l = tid & 31;

    float kn0 = knots[0];
    float kn14 = knots[NKNOTS - 1];
    float inv_h = 14.0f / (kn14 - kn0);

    float g0 = gamma[h * HD + l], g1 = gamma[h * HD + l + 32];
    float be0 = beta[h * HD + l], be1 = beta[h * HD + l + 32];

    for (int idx = tid; idx < NB * HD; idx += 512)
        Wsbuf[idx] = coeff[(size_t)h * NB * HD + idx];

    const float *Qb = g_Q + (size_t)bh * SS * HD;
    const float *Kb = g_K + (size_t)bh * SS * HD;
    const float *Vb = g_V + (size_t)bh * SS * HD;
    const float *eb = g_eta + (size_t)bh * NMB * MB;
    float *Yb = g_Y + (size_t)b * SS * DIM + h * HD;

    float *cbase = tokbuf + (tid >> 4) * HD + ((tid & 15) << 2);
    float *mb = tokbuf + m * TPITCH;

    int cur = 0;
    __syncthreads();

    int base0 = m * HD + l;
    float q0 = Qb[base0], q1 = Qb[base0 + 32];
    float k0 = Kb[base0], k1 = Kb[base0 + 32];
    float v0 = Vb[base0], v1 = Vb[base0 + 32];
    float e  = eb[m];

    for (int n = 0; n < NMB; n++) {
        float cq0 = q0, cq1 = q1, ck0 = k0, ck1 = k1, cv0 = v0, cv1 = v1, ce = e;
        int np = (n + 1 < NMB) ? n + 1 : n;
        int basen = (np * MB + m) * HD + l;
        q0 = Qb[basen]; q1 = Qb[basen + 32];
        k0 = Kb[basen]; k1 = Kb[basen + 32];
        v0 = Vb[basen]; v1 = Vb[basen + 32];
        e  = eb[np * MB + m];

        const float *Wc = Wsbuf + cur * (NB * HD);
        float *Wn = Wsbuf + (cur ^ 1) * (NB * HD);

        int jk0, jk1;
        float wk0[4], wk1[4];
        bspline4(ck0, kn0, inv_h, jk0, wk0);
        bspline4(ck1, kn0, inv_h, jk1, wk1);

        float z0 = __fdividef(ck0, 1.0f + __expf(-ck0));
        float z1 = __fdividef(ck1, 1.0f + __expf(-ck1));
#pragma unroll
        for (int k = 0; k < 4; k++) {
            z0 = fmaf(wk0[k], Wc[clampj(jk0 + k) * HD + l], z0);
            z1 = fmaf(wk1[k], Wc[clampj(jk1 + k) * HD + l + 32], z1);
        }
        float s1 = z0 + z1, s2 = fmaf(z0, z0, z1 * z1);
        wsum2(s1, s2);
        float mu = s1 * (1.f / 64.f);
        float var = s2 * (1.f / 64.f) - mu * mu;
        float rstd = rsqrtf(var + EPSV);
        float xh0 = (z0 - mu) * rstd, xh1 = (z1 - mu) * rstd;
        float gh0 = (fmaf(g0, xh0, be0) - (cv0 - ck0)) * g0;
        float gh1 = (fmaf(g1, xh1, be1) - (cv1 - ck1)) * g1;
        s1 = gh0 + gh1;
        s2 = fmaf(gh0, xh0, gh1 * xh1);
        wsum2(s1, s2);
        float mg = s1 * (1.f / 64.f), mgx = s2 * (1.f / 64.f);
        float eg0 = ce * (gh0 - mg - xh0 * mgx) * rstd;
        float eg1 = ce * (gh1 - mg - xh1 * mgx) * rstd;

        float4 z4 = make_float4(0.f, 0.f, 0.f, 0.f);
#pragma unroll
        for (int i = 0; i < 6; i++)
            ((float4 *)mb)[i * 32 + l] = z4;
        __syncwarp();
#pragma unroll
        for (int k = 0; k < 4; k++) {
            if (wk0[k] != 0.f) mb[(jk0 + k) * HD + l] = eg0 * wk0[k];
            if (wk1[k] != 0.f) mb[(jk1 + k) * HD + l + 32] = eg1 * wk1[k];
        }
        __syncthreads();

        // ---- phase B: cumsum over m, register-batched (2 x 8) ----
        if (tid < 176) {
            float4 vv[8];
            float4 carry = make_float4(0.f, 0.f, 0.f, 0.f);
#pragma unroll
            for (int blk = 0; blk < 2; blk++) {
                float *p = cbase + blk * 8 * TPITCH;
#pragma unroll
                for (int mm = 0; mm < 8; mm++)
                    vv[mm] = *(float4 *)(p + mm * TPITCH);
                vv[0].x += carry.x; vv[0].y += carry.y;
                vv[0].z += carry.z; vv[0].w += carry.w;
#pragma unroll
                for (int mm = 1; mm < 8; mm++) {
                    vv[mm].x += vv[mm - 1].x; vv[mm].y += vv[mm - 1].y;
                    vv[mm].z += vv[mm - 1].z; vv[mm].w += vv[mm - 1].w;
                }
#pragma unroll
                for (int mm = 0; mm < 8; mm++)
                    *(float4 *)(p + mm * TPITCH) = vv[mm];
                carry = vv[7];
            }
        }
        __syncthreads();

        int jq0, jq1;
        float wq0[4], wq1[4];
        bspline4(cq0, kn0, inv_h, jq0, wq0);
        bspline4(cq1, kn0, inv_h, jq1, wq1);
        float zq0 = __fdividef(cq0, 1.0f + __expf(-cq0));
        float zq1 = __fdividef(cq1, 1.0f + __expf(-cq1));
#pragma unroll
        for (int k = 0; k < 4; k++) {
            int ja = clampj(jq0 + k) * HD + l;
            int jb = clampj(jq1 + k) * HD + l + 32;
            zq0 = fmaf(wq0[k], Wc[ja] - mb[ja], zq0);
            zq1 = fmaf(wq1[k], Wc[jb] - mb[jb], zq1);
        }
        s1 = zq0 + zq1;
        s2 = fmaf(zq0, zq0, zq1 * zq1);
        wsum2(s1, s2);
        mu = s1 * (1.f / 64.f);
        var = s2 * (1.f / 64.f) - mu * mu;
        rstd = rsqrtf(var + EPSV);
        float y0 = cq0 + fmaf(g0, (zq0 - mu) * rstd, be0);
        float y1 = cq1 + fmaf(g1, (zq1 - mu) * rstd, be1);

        size_t yo = (size_t)(n * MB + m) * DIM;
        Yb[yo + l] = y0;
        Yb[yo + l + 32] = y1;

        if (tid < 176) {
            const float4 wv = *(const float4 *)(Wc + tid * 4);
            const float4 cv = *(const float4 *)(tokbuf + 15 * TPITCH + tid * 4);
            float4 r;
            r.x = wv.x - cv.x; r.y = wv.y - cv.y;
            r.z = wv.z - cv.z; r.w = wv.w - cv.w;
            *(float4 *)(Wn + tid * 4) = r;
        }
        __syncthreads();
        cur ^= 1;
    }
}

// ---------------------------------------------------------------------------
// LN row stats only (mu, rstd per row); apply fused into tc_out staging
// ---------------------------------------------------------------------------
__global__ __launch_bounds__(256) void ln_stats_kernel() {
    int row = blockIdx.x;
    int tid = threadIdx.x;
    float4 v = *((const float4 *)(g_Y + (size_t)row * 1024) + tid);
    float s1 = v.x + v.y + v.z + v.w;
    float s2 = v.x * v.x + v.y * v.y + v.z * v.z + v.w * v.w;
    wsum2(s1, s2);
    __shared__ float sa[8], sb[8];
    int w = tid >> 5, l = tid & 31;
    if (l == 0) { sa[w] = s1; sb[w] = s2; }
    __syncthreads();
    if (tid == 0) {
        s1 = 0.f; s2 = 0.f;
#pragma unroll
        for (int i = 0; i < 8; i++) { s1 += sa[i]; s2 += sb[i]; }
        float mu = s1 * (1.f / 1024.f);
        float var = s2 * (1.f / 1024.f) - mu * mu;
        g_mu[row] = mu;
        g_rs[row] = rsqrtf(var + EPSV);
    }
}

// ---------------------------------------------------------------------------
// Launch
// ---------------------------------------------------------------------------
extern "C" void kernel_launch(void *const *d_in, const int *in_sizes, int n_in,
                              void *d_out, int out_size) {
    const float *x     = (const float *)d_in[0];
    const float *posf  = (const float *)d_in[1];
    const float *Wq    = (const float *)d_in[2];
    const float *Wk    = (const float *)d_in[3];
    const float *Wv    = (const float *)d_in[4];
    const float *Wo    = (const float *)d_in[5];
    const float *lrW   = (const float *)d_in[6];
    const float *lrb   = (const float *)d_in[7];
    const float *gsc   = (const float *)d_in[8];
    const float *tgam  = (const float *)d_in[9];
    const float *tbet  = (const float *)d_in[10];
    const float *postw = (const float *)d_in[11];
    const float *postb = (const float *)d_in[12];
    const float *coeff = (const float *)d_in[13];
    const float *knots = (const float *)d_in[14];
    float *out = (float *)d_out;

    const int scan_smem = (MB * TPITCH + 2 * NB * HD) * sizeof(float);  // 54784 B
    cudaFuncSetAttribute(scan_kernel, cudaFuncAttributeMaxDynamicSharedMemorySize,
                         scan_smem);

    rope_tab_kernel<<<(SS * (HD / 2) + 1023) / 1024, 1024>>>(posf);
    tc_qkv_kernel<<<dim3(DIM / 128, BB * SS / 128, 3), 256>>>(x, Wq, Wk, Wv);
    eta_kernel<<<BB * SS, 128>>>(x, lrW, lrb, gsc);
    scan_kernel<<<BB * HH, 512, scan_smem>>>(tgam, tbet, knots, coeff);
    ln_stats_kernel<<<BB * SS, 256>>>();
    tc_out_kernel<<<dim3(DIM / 128, BB * SS / 128, 1), 256>>>(Wo, postw, postb, out);
}